// round 6
// baseline (speedup 1.0000x reference)
#include <cuda_runtime.h>

#define Dq 512
#define Hq 64
#define NN 40
#define EMAX 104
#define BMAX 8192
#define NTHREADS 512
#define AST 44          // A row stride

typedef unsigned long long ull;

// ---------------- device scratch ----------------
__device__ float g_M1[Dq * Hq];      // Wg@W1   [k][h]
__device__ float g_M2[Dq * Hq];      // Wg@W2   [k][h]
__device__ float g_M3T[Hq * 1040];   // [h][k] k<1024, stride 1040
__device__ float g_c[Hq];
__device__ float g_d3[Hq];
__device__ float g_e3[Hq];
__device__ float g_Y[(size_t)BMAX * NN * Hq];  // hidden @ M2
__device__ float g_VS[BMAX * 1024];  // [v_n(512), sP(512)]
__device__ float g_A[BMAX];
__device__ int g_node_off[BMAX + 1];
__device__ int g_tok_off[BMAX + 1];

__device__ __forceinline__ void ffma2(ull& a, ull x, ull y) {
    asm("fma.rn.f32x2 %0, %1, %2, %0;" : "+l"(a) : "l"(x), "l"(y));
}
__device__ __forceinline__ ull splat2(float v) {
    ull r; asm("mov.b64 %0, {%1, %1};" : "=l"(r) : "f"(v)); return r;
}
__device__ __forceinline__ float2 unpk(ull v) {
    float2 r; asm("mov.b64 {%0, %1}, %2;" : "=f"(r.x), "=f"(r.y) : "l"(v)); return r;
}

// ---------------- prelude ----------------
__global__ void k_mark(const int* __restrict__ batch, int N) {
    int i = blockIdx.x * blockDim.x + threadIdx.x;
    if (i < N) {
        if (i == 0 || batch[i] != batch[i - 1]) g_node_off[batch[i]] = i;
    }
}

__global__ void k_scan(const int* __restrict__ seq_len, int B, int N) {
    __shared__ int wsum[32];
    __shared__ int carry_s;
    if (threadIdx.x == 0) { carry_s = 0; g_node_off[B] = N; }
    __syncthreads();
    for (int base = 0; base < B; base += 1024) {
        int i = base + (int)threadIdx.x;
        int v = (i < B) ? seq_len[i] : 0;
        int lane = threadIdx.x & 31, w = threadIdx.x >> 5;
        int x = v;
        for (int o = 1; o < 32; o <<= 1) {
            int y = __shfl_up_sync(0xffffffffu, x, o);
            if (lane >= o) x += y;
        }
        if (lane == 31) wsum[w] = x;
        __syncthreads();
        if (w == 0) {
            int s = wsum[lane];
            for (int o = 1; o < 32; o <<= 1) {
                int y = __shfl_up_sync(0xffffffffu, s, o);
                if (lane >= o) s += y;
            }
            wsum[lane] = s;
        }
        __syncthreads();
        int excl = x - v + (w ? wsum[w - 1] : 0) + carry_s;
        if (i < B) g_tok_off[i] = excl;
        __syncthreads();
        if (threadIdx.x == 0) carry_s = carry_s + wsum[31];
        __syncthreads();
    }
    if (threadIdx.x == 0) g_tok_off[B] = carry_s;
}

__global__ void k_mats(const float* __restrict__ Wg, const float* __restrict__ W1,
                       const float* __restrict__ W2, const float* __restrict__ W3) {
    __shared__ float wg8[8 * Dq];
    int kb = blockIdx.x;
    int m = blockIdx.y;
    const float* W;
    if (m == 0)      W = W1;
    else if (m == 1) W = W2;
    else if (m == 2) W = W3;
    else             W = W3 + Dq * Hq;
    for (int i = threadIdx.x; i < 8 * Dq; i += 256) wg8[i] = Wg[kb * 8 * Dq + i];
    __syncthreads();
    int h = threadIdx.x & 63;
    int r0 = threadIdx.x >> 6;
    float a0 = 0.f, a1 = 0.f;
    for (int d = 0; d < Dq; d++) {
        float wv = W[d * Hq + h];
        a0 += wg8[r0 * Dq + d] * wv;
        a1 += wg8[(r0 + 4) * Dq + d] * wv;
    }
    int row0 = kb * 8 + r0, row1 = kb * 8 + r0 + 4;
    if (m == 0)      { g_M1[row0 * Hq + h] = a0; g_M1[row1 * Hq + h] = a1; }
    else if (m == 1) { g_M2[row0 * Hq + h] = a0; g_M2[row1 * Hq + h] = a1; }
    else {
        int off = (m == 3) ? 512 : 0;
        g_M3T[h * 1040 + off + row0] = a0;
        g_M3T[h * 1040 + off + row1] = a1;
    }
}

__global__ void k_vecs(const float* __restrict__ bg, const float* __restrict__ b1,
                       const float* __restrict__ b2, const float* __restrict__ b3,
                       const float* __restrict__ W1, const float* __restrict__ W2,
                       const float* __restrict__ W3) {
    __shared__ float red[3][128];
    int h = blockIdx.x, t = threadIdx.x;
    float cv = 0.f, dv = 0.f, ev = 0.f;
    for (int d = t; d < Dq; d += 128) {
        float bgv = bg[d];
        cv += bgv * (W1[d * Hq + h] + W2[d * Hq + h]);
        dv += bgv * W3[d * Hq + h];
        ev += bgv * W3[(Dq + d) * Hq + h];
    }
    red[0][t] = cv; red[1][t] = dv; red[2][t] = ev;
    __syncthreads();
    for (int s = 64; s; s >>= 1) {
        if (t < s) {
            red[0][t] += red[0][t + s];
            red[1][t] += red[1][t + s];
            red[2][t] += red[2][t + s];
        }
        __syncthreads();
    }
    if (t == 0) {
        g_c[h] = red[0][0] + b1[h] + b2[h];
        g_d3[h] = red[1][0] + b3[h];
        g_e3[h] = red[2][0];
    }
}

// ---------------- big dense GEMM: g_Y = hidden @ M2 ----------------
// tile: 128 rows x 64 cols, K chunks of 32, double-buffered.
__global__ void __launch_bounds__(256, 2) k_gemm(const float* __restrict__ hidden) {
    __shared__ float a_s[2][32 * 130];
    __shared__ float b_s[2][32 * 64];
    int tid = threadIdx.x;
    int row0 = blockIdx.x * 128;
    int kq = tid & 7, rr = tid >> 3;            // A-load: 8 kq x 32 rows
    int r0 = (tid >> 4) * 8, c4 = (tid & 15) * 4;
    const float4* h4 = (const float4*)(hidden + (size_t)row0 * Dq);
    const float4* m4 = (const float4*)g_M2;

    // chunk 0 direct load
    {
#pragma unroll
        for (int it = 0; it < 4; it++) {
            int r = rr + it * 32;
            float4 v = h4[r * 128 + kq];
            a_s[0][(kq * 4 + 0) * 130 + r] = v.x;
            a_s[0][(kq * 4 + 1) * 130 + r] = v.y;
            a_s[0][(kq * 4 + 2) * 130 + r] = v.z;
            a_s[0][(kq * 4 + 3) * 130 + r] = v.w;
        }
#pragma unroll
        for (int it = 0; it < 2; it++) {
            int idx = tid + it * 256;
            int k = idx >> 4, c = idx & 15;
            *(float4*)&b_s[0][k * 64 + c * 4] = m4[k * 16 + c];
        }
    }
    __syncthreads();

    ull acc[4][4];
#pragma unroll
    for (int p = 0; p < 4; p++)
#pragma unroll
        for (int c = 0; c < 4; c++) acc[p][c] = 0ull;

    float4 pa[4], pb[2];
    for (int ch = 0; ch < 16; ch++) {
        int cur = ch & 1;
        if (ch < 15) {
            int kc4 = (ch + 1) * 8;  // in float4 units
#pragma unroll
            for (int it = 0; it < 4; it++) {
                int r = rr + it * 32;
                pa[it] = h4[r * 128 + kc4 + kq];
            }
#pragma unroll
            for (int it = 0; it < 2; it++) {
                int idx = tid + it * 256;
                int k = idx >> 4, c = idx & 15;
                pb[it] = m4[(kc4 * 4 + k) * 16 + c];
            }
        }
        const float* as = a_s[cur];
        const float* bs = b_s[cur];
#pragma unroll 8
        for (int k = 0; k < 32; k++) {
            float4 bv = *(const float4*)(bs + k * 64 + c4);
            ull b0 = splat2(bv.x), b1 = splat2(bv.y);
            ull b2 = splat2(bv.z), b3 = splat2(bv.w);
            const float* ak = as + k * 130 + r0;
            ull a01 = *(const ull*)(ak);
            ull a23 = *(const ull*)(ak + 2);
            ull a45 = *(const ull*)(ak + 4);
            ull a67 = *(const ull*)(ak + 6);
            ffma2(acc[0][0], a01, b0); ffma2(acc[0][1], a01, b1);
            ffma2(acc[0][2], a01, b2); ffma2(acc[0][3], a01, b3);
            ffma2(acc[1][0], a23, b0); ffma2(acc[1][1], a23, b1);
            ffma2(acc[1][2], a23, b2); ffma2(acc[1][3], a23, b3);
            ffma2(acc[2][0], a45, b0); ffma2(acc[2][1], a45, b1);
            ffma2(acc[2][2], a45, b2); ffma2(acc[2][3], a45, b3);
            ffma2(acc[3][0], a67, b0); ffma2(acc[3][1], a67, b1);
            ffma2(acc[3][2], a67, b2); ffma2(acc[3][3], a67, b3);
        }
        if (ch < 15) {
            int nb = cur ^ 1;
#pragma unroll
            for (int it = 0; it < 4; it++) {
                int r = rr + it * 32;
                a_s[nb][(kq * 4 + 0) * 130 + r] = pa[it].x;
                a_s[nb][(kq * 4 + 1) * 130 + r] = pa[it].y;
                a_s[nb][(kq * 4 + 2) * 130 + r] = pa[it].z;
                a_s[nb][(kq * 4 + 3) * 130 + r] = pa[it].w;
            }
#pragma unroll
            for (int it = 0; it < 2; it++) {
                int idx = tid + it * 256;
                int k = idx >> 4, c = idx & 15;
                *(float4*)&b_s[nb][k * 64 + c * 4] = pb[it];
            }
        }
        __syncthreads();
    }
    // epilogue: rows r0+2p, r0+2p+1 ; cols c4..c4+3
#pragma unroll
    for (int p = 0; p < 4; p++) {
        float2 v0 = unpk(acc[p][0]), v1 = unpk(acc[p][1]);
        float2 v2 = unpk(acc[p][2]), v3 = unpk(acc[p][3]);
        size_t row = (size_t)(row0 + r0 + 2 * p);
        float4 o0 = make_float4(v0.x, v1.x, v2.x, v3.x);
        float4 o1 = make_float4(v0.y, v1.y, v2.y, v3.y);
        *(float4*)&g_Y[row * Hq + c4] = o0;
        *(float4*)&g_Y[(row + 1) * Hq + c4] = o1;
    }
}

// ---------------- per-session kernel (light) ----------------
struct __align__(16) SmemS {
    float X[NN * Dq];      // 81920
    float Ys[NN * Hq];     // 10240
    float A[NN * AST];     // 7040  (also reused as u-reduction scratch)
    float A2[NN * AST];    // 7040
    float z[Dq];           // 2048
    float u[Hq];
    float ew[EMAX];
    float dinv[NN];
    float af[NN];
    float w[NN];
    int es[EMAX], ed[EMAX], pr[EMAX];
    int deg[NN], cnt[NN], act[NN];
    int nact, jlast, lastnode;
};

__global__ void __launch_bounds__(NTHREADS, 2) k_sess(
    const float* __restrict__ hidden, const float* __restrict__ Wq,
    const float* __restrict__ bq, const int* __restrict__ eidx,
    const int* __restrict__ sidx, const int* __restrict__ seq_len,
    int E, int B) {
    extern __shared__ unsigned char smraw[];
    SmemS* S = (SmemS*)smraw;
    int b = blockIdx.x, tid = threadIdx.x;
    int nbase = g_node_off[b];
    int nn = g_node_off[b + 1] - nbase;
    int eps = E / B;
    int ne = eps + nn;
    int tbase = g_tok_off[b];
    int sl = seq_len[b];

    // phase 1: loads + zeroing + edge decode
    if (tid < NN) { S->deg[tid] = 0; S->cnt[tid] = 0; }
    for (int i = tid; i < NN * AST; i += NTHREADS) S->A[i] = 0.f;
    {
        const float4* src = (const float4*)(hidden + (size_t)nbase * Dq);
        float4* dst = (float4*)S->X;
        int cnt4 = nn * (Dq / 4);
        for (int i = tid; i < cnt4; i += NTHREADS) dst[i] = src[i];
        for (int i = nn * Dq + tid; i < NN * Dq; i += NTHREADS) S->X[i] = 0.f;
        const float4* ysrc = (const float4*)(g_Y + (size_t)nbase * Hq);
        float4* ydst = (float4*)S->Ys;
        int ycnt4 = nn * (Hq / 4);
        for (int i = tid; i < ycnt4; i += NTHREADS) ydst[i] = ysrc[i];
        for (int i = nn * Hq + tid; i < NN * Hq; i += NTHREADS) S->Ys[i] = 0.f;
    }
    for (int e = tid; e < ne; e += NTHREADS) {
        int s, d;
        if (e < eps) {
            s = eidx[(size_t)b * eps + e] - nbase;
            d = eidx[(size_t)E + (size_t)b * eps + e] - nbase;
        } else {
            s = d = e - eps;
        }
        S->es[e] = s; S->ed[e] = d;
    }
    if (tid == 0) S->lastnode = sidx[tbase + sl - 1];
    __syncthreads();
    // phase 2: histograms + pair pack
    for (int e = tid; e < ne; e += NTHREADS) {
        atomicAdd(&S->deg[S->ed[e]], 1);
        S->pr[e] = S->ed[e] * 64 + S->es[e];
    }
    for (int t = tid; t < sl; t += NTHREADS) atomicAdd(&S->cnt[sidx[tbase + t]], 1);
    __syncthreads();
    if (tid < nn) S->dinv[tid] = rsqrtf((float)S->deg[tid]);
    __syncthreads();
    for (int e = tid; e < ne; e += NTHREADS)
        S->ew[e] = S->dinv[S->es[e]] * S->dinv[S->ed[e]];
    if (tid == 32) {
        int ln = S->lastnode;
        int na = 0, jl = 0;
        for (int n2 = 0; n2 < nn; n2++)
            if (S->cnt[n2] > 0) {
                if (n2 == ln) jl = na;
                S->act[na++] = n2;
            }
        S->nact = na;
        S->jlast = jl;
    }
    __syncthreads();
    // phase 5: dense A build (parallel, deterministic index order)
    for (int e = tid; e < ne; e += NTHREADS) {
        int p = S->pr[e];
        bool first = true;
        for (int q = 0; q < e; q++)
            if (S->pr[q] == p) { first = false; break; }
        if (first) {
            float s = S->ew[e];
            for (int q = e + 1; q < ne; q++)
                if (S->pr[q] == p) s += S->ew[q];
            S->A[(p >> 6) * AST + (p & 63)] = s;
        }
    }
    __syncthreads();
    int nact = S->nact;
    int jlast = S->jlast;
    // phase 6: A2act[j][rc] = A[act_j] . A[:,rc]
    for (int c = tid; c < nact * NN; c += NTHREADS) {
        int j = c / NN, rc = c - j * NN;
        const float* Aj = S->A + S->act[j] * AST;
        float s = 0.f;
#pragma unroll 8
        for (int r = 0; r < NN; r++) s += Aj[r] * S->A[r * AST + rc];
        S->A2[j * AST + rc] = s;
    }
    __syncthreads();
    // phase 7: z = A2[jlast] @ X
    {
        const float* a2 = S->A2 + jlast * AST;
        float s = 0.f;
#pragma unroll 8
        for (int r = 0; r < NN; r++) s += a2[r] * S->X[r * Dq + tid];
        S->z[tid] = s;
    }
    __syncthreads();
    // phase 8: u partials (A region reused as scratch)
    {
        int h = tid & 63, k8 = tid >> 6;
        const float* m1 = g_M1 + (k8 * 64) * Hq + h;
        const float* zz = S->z + k8 * 64;
        float s = 0.f;
#pragma unroll 8
        for (int kk = 0; kk < 64; kk++) s += zz[kk] * m1[kk * Hq];
        S->A[k8 * 64 + h] = s;
    }
    __syncthreads();
    if (tid < Hq) {
        float s = g_c[tid];
#pragma unroll
        for (int k8 = 0; k8 < 8; k8++) s += S->A[k8 * 64 + tid];
        S->u[tid] = s;
    }
    __syncthreads();
    // phase 10: alpha per active node
    {
        int lane = tid & 31, wp = tid >> 5;
        float bq0 = bq[0];
        float wql = Wq[lane], wqh = Wq[lane + 32];
        float ul = S->u[lane], uh = S->u[lane + 32];
        for (int j = wp; j < nact; j += 16) {
            const float* a2 = S->A2 + j * AST;
            float x1 = ul, x2 = uh;
#pragma unroll 8
            for (int r = 0; r < NN; r++) {
                float av = a2[r];
                x1 += av * S->Ys[r * Hq + lane];
                x2 += av * S->Ys[r * Hq + lane + 32];
            }
            float s = wql / (1.f + __expf(-x1)) + wqh / (1.f + __expf(-x2));
            for (int o = 16; o; o >>= 1) s += __shfl_xor_sync(0xffffffffu, s, o);
            if (lane == 0) S->af[j] = (s + bq0) * (float)S->cnt[S->act[j]];
        }
    }
    __syncthreads();
    if (tid == 0) {
        float A = 0.f;
        for (int j = 0; j < nact; j++) A += S->af[j];
        g_A[b] = A;
    }
    if (tid < NN) {
        float s = 0.f;
        for (int j = 0; j < nact; j++) s += S->af[j] * S->A2[j * AST + tid];
        S->w[tid] = s;
    }
    __syncthreads();
    // phase 12: sP + store VS
    {
        float s = 0.f;
#pragma unroll 8
        for (int r = 0; r < NN; r++) s += S->w[r] * S->X[r * Dq + tid];
        g_VS[(size_t)b * 1024 + tid] = S->z[tid];
        g_VS[(size_t)b * 1024 + 512 + tid] = s;
    }
}

// ---------------- final matvec: out = VS @ M3 + d3 + A*e3 ----------------
#define FB 16
#define MS 132
__global__ void __launch_bounds__(256) k_final(float* __restrict__ out, int B) {
    extern __shared__ float fsm[];
    float* vs = fsm;               // FB * 1024
    float* mch = fsm + FB * 1024;  // 64 * MS
    int sb = blockIdx.x * FB;
    int tid = threadIdx.x;
    {
        const float4* src = (const float4*)(g_VS + (size_t)sb * 1024);
        float4* dst = (float4*)vs;
        for (int i = tid; i < FB * 256; i += 256) dst[i] = src[i];
    }
    int h = tid & 63, sg = tid >> 6;
    float acc[4] = {0.f, 0.f, 0.f, 0.f};
    const float* vsr0 = vs + (sg * 4 + 0) * 1024;
    const float* vsr1 = vs + (sg * 4 + 1) * 1024;
    const float* vsr2 = vs + (sg * 4 + 2) * 1024;
    const float* vsr3 = vs + (sg * 4 + 3) * 1024;
    for (int kc = 0; kc < 1024; kc += 128) {
        __syncthreads();
        for (int i = tid; i < 64 * 32; i += 256) {
            int r = i >> 5, c = i & 31;
            float4 v = *(const float4*)(g_M3T + r * 1040 + kc + c * 4);
            *(float4*)(mch + r * MS + c * 4) = v;
        }
        __syncthreads();
#pragma unroll 8
        for (int kk = 0; kk < 128; kk += 4) {
            float4 m = *(const float4*)(mch + h * MS + kk);
            float4 a0 = *(const float4*)(vsr0 + kc + kk);
            float4 a1 = *(const float4*)(vsr1 + kc + kk);
            float4 a2 = *(const float4*)(vsr2 + kc + kk);
            float4 a3 = *(const float4*)(vsr3 + kc + kk);
            acc[0] += a0.x * m.x + a0.y * m.y + a0.z * m.z + a0.w * m.w;
            acc[1] += a1.x * m.x + a1.y * m.y + a1.z * m.z + a1.w * m.w;
            acc[2] += a2.x * m.x + a2.y * m.y + a2.z * m.z + a2.w * m.w;
            acc[3] += a3.x * m.x + a3.y * m.y + a3.z * m.z + a3.w * m.w;
        }
    }
    float d3 = g_d3[h], e3 = g_e3[h];
#pragma unroll
    for (int i = 0; i < 4; i++) {
        int b = sb + sg * 4 + i;
        if (b < B) out[(size_t)b * Hq + h] = acc[i] + d3 + g_A[b] * e3;
    }
}

// ---------------- launch ----------------
extern "C" void kernel_launch(void* const* d_in, const int* in_sizes, int n_in,
                              void* d_out, int out_size) {
    const float* hidden = (const float*)d_in[0];
    const float* Wg = (const float*)d_in[1];
    const float* bg = (const float*)d_in[2];
    const float* W1 = (const float*)d_in[3];
    const float* b1 = (const float*)d_in[4];
    const float* W2 = (const float*)d_in[5];
    const float* b2 = (const float*)d_in[6];
    const float* Wq = (const float*)d_in[7];
    const float* bq = (const float*)d_in[8];
    const float* W3 = (const float*)d_in[9];
    const float* b3 = (const float*)d_in[10];
    const int* eidx = (const int*)d_in[11];
    const int* batch = (const int*)d_in[12];
    const int* sidx = (const int*)d_in[13];
    const int* seql = (const int*)d_in[14];

    int N = in_sizes[0] / Dq;
    int B = in_sizes[14];
    int E = in_sizes[11] / 2;
    float* out = (float*)d_out;

    k_mark<<<(N + 255) / 256, 256>>>(batch, N);
    k_scan<<<1, 1024>>>(seql, B, N);
    dim3 gm(Dq / 8, 4);
    k_mats<<<gm, 256>>>(Wg, W1, W2, W3);
    k_vecs<<<Hq, 128>>>(bg, b1, b2, b3, W1, W2, W3);

    k_gemm<<<(N + 127) / 128, 256>>>(hidden);

    cudaFuncSetAttribute(k_sess, cudaFuncAttributeMaxDynamicSharedMemorySize,
                         (int)sizeof(SmemS));
    k_sess<<<B, NTHREADS, sizeof(SmemS)>>>(hidden, Wq, bq, eidx, sidx, seql, E, B);

    int fsmem = (FB * 1024 + 64 * MS) * (int)sizeof(float);
    cudaFuncSetAttribute(k_final, cudaFuncAttributeMaxDynamicSharedMemorySize, fsmem);
    k_final<<<(B + FB - 1) / FB, 256, fsmem>>>(out, B);
}

// round 9
// speedup vs baseline: 1.4153x; 1.4153x over previous
#include <cuda_runtime.h>

#define Dq 512
#define Hq 64
#define NN 40
#define EMAX 104
#define BMAX 8192
#define NTH 256
#define AST 42

typedef unsigned long long ull;

// ---------------- device scratch ----------------
__device__ float g_M1[Dq * Hq];      // Wg@W1   [k][h]
__device__ float g_M2[Dq * Hq];      // Wg@W2   [k][h]
__device__ float g_M3T[Hq * 1040];   // [h][k] k<1024, stride 1040
__device__ float g_c[Hq];
__device__ float g_d3[Hq];
__device__ float g_e3[Hq];
__device__ float g_VS[BMAX * 1024];  // [v_n(512), sP(512)]
__device__ float g_A[BMAX];
__device__ int g_node_off[BMAX + 1];
__device__ int g_tok_off[BMAX + 1];

__device__ __forceinline__ void ffma2(ull& a, ull x, ull y) {
    asm("fma.rn.f32x2 %0, %1, %2, %0;" : "+l"(a) : "l"(x), "l"(y));
}
__device__ __forceinline__ ull splat2(float v) {
    ull r; asm("mov.b64 %0, {%1, %1};" : "=l"(r) : "f"(v)); return r;
}
__device__ __forceinline__ float2 unpk(ull v) {
    float2 r; asm("mov.b64 {%0, %1}, %2;" : "=f"(r.x), "=f"(r.y) : "l"(v)); return r;
}

struct __align__(16) SmemS {
    float st[32 * 68];    // M2 chunk stage
    float XC[NN * 68];    // X chunk stage (32 k)
    float Y[NN * Hq];     // GEMM output
    float A[NN * AST];
    float A2[NN * AST];
    float z[Dq];
    float u[Hq];
    float scr[256];
    float ew[EMAX];
    float dinv[NN];
    float af[NN];
    float w[NN];
    int es[EMAX], ed[EMAX];
    int deg[NN], cnt[NN], act[NN];
    int nact, jlast, lastnode;
};

// ---------------- prelude ----------------
__global__ void k_mark(const int* __restrict__ batch, int N) {
    int i = blockIdx.x * blockDim.x + threadIdx.x;
    if (i < N) {
        if (i == 0 || batch[i] != batch[i - 1]) g_node_off[batch[i]] = i;
    }
}

__global__ void k_scan(const int* __restrict__ seq_len, int B, int N) {
    __shared__ int wsum[32];
    __shared__ int carry_s;
    if (threadIdx.x == 0) { carry_s = 0; g_node_off[B] = N; }
    __syncthreads();
    for (int base = 0; base < B; base += 1024) {
        int i = base + (int)threadIdx.x;
        int v = (i < B) ? seq_len[i] : 0;
        int lane = threadIdx.x & 31, w = threadIdx.x >> 5;
        int x = v;
        for (int o = 1; o < 32; o <<= 1) {
            int y = __shfl_up_sync(0xffffffffu, x, o);
            if (lane >= o) x += y;
        }
        if (lane == 31) wsum[w] = x;
        __syncthreads();
        if (w == 0) {
            int s = wsum[lane];
            for (int o = 1; o < 32; o <<= 1) {
                int y = __shfl_up_sync(0xffffffffu, s, o);
                if (lane >= o) s += y;
            }
            wsum[lane] = s;
        }
        __syncthreads();
        int excl = x - v + (w ? wsum[w - 1] : 0) + carry_s;
        if (i < B) g_tok_off[i] = excl;
        __syncthreads();
        if (threadIdx.x == 0) carry_s = carry_s + wsum[31];
        __syncthreads();
    }
    if (threadIdx.x == 0) g_tok_off[B] = carry_s;
}

__global__ void k_mats(const float* __restrict__ Wg, const float* __restrict__ W1,
                       const float* __restrict__ W2, const float* __restrict__ W3) {
    __shared__ float wg8[8 * Dq];
    int kb = blockIdx.x;
    int m = blockIdx.y;
    const float* W;
    if (m == 0)      W = W1;
    else if (m == 1) W = W2;
    else if (m == 2) W = W3;
    else             W = W3 + Dq * Hq;
    for (int i = threadIdx.x; i < 8 * Dq; i += 256) wg8[i] = Wg[kb * 8 * Dq + i];
    __syncthreads();
    int h = threadIdx.x & 63;
    int r0 = threadIdx.x >> 6;
    float a0 = 0.f, a1 = 0.f;
    for (int d = 0; d < Dq; d++) {
        float wv = W[d * Hq + h];
        a0 += wg8[r0 * Dq + d] * wv;
        a1 += wg8[(r0 + 4) * Dq + d] * wv;
    }
    int row0 = kb * 8 + r0, row1 = kb * 8 + r0 + 4;
    if (m == 0)      { g_M1[row0 * Hq + h] = a0; g_M1[row1 * Hq + h] = a1; }
    else if (m == 1) { g_M2[row0 * Hq + h] = a0; g_M2[row1 * Hq + h] = a1; }
    else {
        int off = (m == 3) ? 512 : 0;
        g_M3T[h * 1040 + off + row0] = a0;
        g_M3T[h * 1040 + off + row1] = a1;
    }
}

__global__ void k_vecs(const float* __restrict__ bg, const float* __restrict__ b1,
                       const float* __restrict__ b2, const float* __restrict__ b3,
                       const float* __restrict__ W1, const float* __restrict__ W2,
                       const float* __restrict__ W3) {
    __shared__ float red[3][128];
    int h = blockIdx.x, t = threadIdx.x;
    float cv = 0.f, dv = 0.f, ev = 0.f;
    for (int d = t; d < Dq; d += 128) {
        float bgv = bg[d];
        cv += bgv * (W1[d * Hq + h] + W2[d * Hq + h]);
        dv += bgv * W3[d * Hq + h];
        ev += bgv * W3[(Dq + d) * Hq + h];
    }
    red[0][t] = cv; red[1][t] = dv; red[2][t] = ev;
    __syncthreads();
    for (int s = 64; s; s >>= 1) {
        if (t < s) {
            red[0][t] += red[0][t + s];
            red[1][t] += red[1][t + s];
            red[2][t] += red[2][t + s];
        }
        __syncthreads();
    }
    if (t == 0) {
        g_c[h] = red[0][0] + b1[h] + b2[h];
        g_d3[h] = red[1][0] + b3[h];
        g_e3[h] = red[2][0];
    }
}

// ---------------- per-session fused kernel, occ 4 ----------------
__global__ void __launch_bounds__(NTH, 4) k_main(
    const float* __restrict__ hidden, const float* __restrict__ Wq,
    const float* __restrict__ bq, const int* __restrict__ eidx,
    const int* __restrict__ sidx, const int* __restrict__ seq_len,
    int E, int B) {
    extern __shared__ unsigned char smraw[];
    SmemS* S = (SmemS*)smraw;
    int b = blockIdx.x, tid = threadIdx.x;
    int nbase = g_node_off[b];
    int nn = g_node_off[b + 1] - nbase;
    int eps = E / B;
    int ne = eps + nn;
    int tbase = g_tok_off[b];
    int sl = seq_len[b];

    // phase 0: init + edge decode
    if (tid < NN) { S->deg[tid] = 0; S->cnt[tid] = 0; }
    for (int i = tid; i < NN * AST; i += NTH) S->A[i] = 0.f;
    for (int e = tid; e < ne; e += NTH) {
        int s, d;
        if (e < eps) {
            s = eidx[(size_t)b * eps + e] - nbase;
            d = eidx[(size_t)E + (size_t)b * eps + e] - nbase;
        } else {
            s = d = e - eps;
        }
        S->es[e] = s; S->ed[e] = d;
    }
    if (tid == 0) S->lastnode = sidx[tbase + sl - 1];
    __syncthreads();
    // phase 1: histograms
    for (int e = tid; e < ne; e += NTH) atomicAdd(&S->deg[S->ed[e]], 1);
    for (int t = tid; t < sl; t += NTH) atomicAdd(&S->cnt[sidx[tbase + t]], 1);
    __syncthreads();
    if (tid < nn) S->dinv[tid] = rsqrtf((float)S->deg[tid]);
    __syncthreads();
    for (int e = tid; e < ne; e += NTH)
        S->ew[e] = S->dinv[S->es[e]] * S->dinv[S->ed[e]];
    if (tid == 64) {
        int ln = S->lastnode;
        int na = 0, jl = 0;
        for (int n2 = 0; n2 < nn; n2++)
            if (S->cnt[n2] > 0) {
                if (n2 == ln) jl = na;
                S->act[na++] = n2;
            }
        S->nact = na;
        S->jlast = jl;
    }
    __syncthreads();
    // phase 2: dense A (deterministic per-target scan)
    if (tid < nn) {
        float* Arow = S->A + tid * AST;
        for (int e = 0; e < ne; e++)
            if (S->ed[e] == tid) Arow[S->es[e]] += S->ew[e];
    }
    __syncthreads();
    int nact = S->nact, jlast = S->jlast;
    // phase 3: A2act[j][rc]
    for (int c = tid; c < nact * NN; c += NTH) {
        int j = c / NN, rc = c - j * NN;
        const float* Aj = S->A + S->act[j] * AST;
        float s = 0.f;
#pragma unroll 8
        for (int r = 0; r < NN; r++) s += Aj[r] * S->A[r * AST + rc];
        S->A2[j * AST + rc] = s;
    }
    __syncthreads();

    // phase 4: GEMM Y = X@M2, streaming X in 32-k chunks from global
    {
        int h4 = tid & 15, jg = (tid >> 4) & 7, ks = tid >> 7;
        int lh = h4 * 4, r0 = jg * 5, kl = ks * 16;
        const float4* hg = (const float4*)hidden;
        const float4* m4 = (const float4*)g_M2;
        ull acc[5][2];
#pragma unroll
        for (int i = 0; i < 5; i++) { acc[i][0] = 0ull; acc[i][1] = 0ull; }
        bool a1v = (tid < 64);
        int mk = tid >> 4, mc = tid & 15;     // M2 loader coords
        int xr = tid >> 3, xq = tid & 7;      // XC loader coords
        int xr2 = (tid + 256) >> 3;
        float4 pb0, pb1, pa0, pa1;
        float4 fz = make_float4(0.f, 0.f, 0.f, 0.f);
        // prefetch chunk 0
        pb0 = m4[mk * 16 + mc];
        pb1 = m4[(16 + mk) * 16 + mc];
        pa0 = (xr < nn) ? hg[(size_t)(nbase + xr) * 128 + xq] : fz;
        pa1 = (a1v && xr2 < nn) ? hg[(size_t)(nbase + xr2) * 128 + xq] : fz;
        for (int ch = 0; ch < 16; ch++) {
            *(float4*)&S->st[mk * 68 + mc * 4] = pb0;
            *(float4*)&S->st[(16 + mk) * 68 + mc * 4] = pb1;
            *(float4*)&S->XC[xr * 68 + xq * 4] = pa0;
            if (a1v) *(float4*)&S->XC[xr2 * 68 + xq * 4] = pa1;
            __syncthreads();
            if (ch < 15) {
                int cb = (ch + 1) * 32, ca = (ch + 1) * 8;
                pb0 = m4[(cb + mk) * 16 + mc];
                pb1 = m4[(cb + 16 + mk) * 16 + mc];
                pa0 = (xr < nn) ? hg[(size_t)(nbase + xr) * 128 + ca + xq] : fz;
                pa1 = (a1v && xr2 < nn) ? hg[(size_t)(nbase + xr2) * 128 + ca + xq] : fz;
            }
#pragma unroll
            for (int q = 0; q < 4; q++) {
                int kk0 = kl + q * 4;
                float4 xv[5];
#pragma unroll
                for (int i = 0; i < 5; i++)
                    xv[i] = *(const float4*)&S->XC[(r0 + i) * 68 + kk0];
#pragma unroll
                for (int kk = 0; kk < 4; kk++) {
                    const ull* mp = (const ull*)&S->st[(kk0 + kk) * 68 + lh];
                    ull m01 = mp[0], m23 = mp[1];
#pragma unroll
                    for (int i = 0; i < 5; i++) {
                        float xs = (kk == 0) ? xv[i].x : (kk == 1) ? xv[i].y
                                 : (kk == 2) ? xv[i].z : xv[i].w;
                        ull xp = splat2(xs);
                        ffma2(acc[i][0], xp, m01);
                        ffma2(acc[i][1], xp, m23);
                    }
                }
            }
            __syncthreads();
        }
        // deterministic 2-round ks reduction into Y
        for (int r = 0; r < 2; r++) {
            if (ks == r) {
#pragma unroll
                for (int i = 0; i < 5; i++)
#pragma unroll
                    for (int p = 0; p < 2; p++) {
                        float2 v = unpk(acc[i][p]);
                        float* yp = &S->Y[(r0 + i) * Hq + lh + 2 * p];
                        if (r == 0) { yp[0] = v.x; yp[1] = v.y; }
                        else { yp[0] += v.x; yp[1] += v.y; }
                    }
            }
            __syncthreads();
        }
    }

    // phase 5: z = A2[jlast] @ X (global reads, L2-warm)
    {
        const float* a2 = S->A2 + jlast * AST;
        for (int k = tid; k < Dq; k += NTH) {
            float s = 0.f;
#pragma unroll 8
            for (int r = 0; r < nn; r++)
                s += a2[r] * hidden[(size_t)(nbase + r) * Dq + k];
            S->z[k] = s;
        }
    }
    __syncthreads();
    // phase 6: u = c + z @ M1
    {
        int h = tid & 63, kg = tid >> 6;
        const float* m1 = g_M1 + (kg * 128) * Hq + h;
        const float* zz = S->z + kg * 128;
        float s = 0.f;
#pragma unroll 8
        for (int kk = 0; kk < 128; kk++) s += zz[kk] * m1[kk * Hq];
        S->scr[kg * 64 + h] = s;
    }
    __syncthreads();
    if (tid < Hq) {
        float s = g_c[tid];
#pragma unroll
        for (int kg = 0; kg < 4; kg++) s += S->scr[kg * 64 + tid];
        S->u[tid] = s;
    }
    __syncthreads();
    // phase 7: alpha per active node
    {
        int lane = tid & 31, wp = tid >> 5;
        float bq0 = bq[0];
        float wql = Wq[lane], wqh = Wq[lane + 32];
        float ul = S->u[lane], uh = S->u[lane + 32];
        for (int j = wp; j < nact; j += 8) {
            const float* a2 = S->A2 + j * AST;
            float x1 = ul, x2 = uh;
#pragma unroll 8
            for (int r = 0; r < NN; r++) {
                float av = a2[r];
                x1 += av * S->Y[r * Hq + lane];
                x2 += av * S->Y[r * Hq + lane + 32];
            }
            float sg = wql / (1.f + __expf(-x1)) + wqh / (1.f + __expf(-x2));
            for (int o = 16; o; o >>= 1) sg += __shfl_xor_sync(0xffffffffu, sg, o);
            if (lane == 0) S->af[j] = (sg + bq0) * (float)S->cnt[S->act[j]];
        }
    }
    __syncthreads();
    if (tid == 0) {
        float A = 0.f;
        for (int j = 0; j < nact; j++) A += S->af[j];
        g_A[b] = A;
    }
    if (tid < NN) {
        float s = 0.f;
        for (int j = 0; j < nact; j++) s += S->af[j] * S->A2[j * AST + tid];
        S->w[tid] = s;
    }
    __syncthreads();
    // phase 8: sP (global reads) + store VS
    for (int k = tid; k < Dq; k += NTH) {
        float s = 0.f;
#pragma unroll 8
        for (int r = 0; r < nn; r++)
            s += S->w[r] * hidden[(size_t)(nbase + r) * Dq + k];
        g_VS[(size_t)b * 1024 + k] = S->z[k];
        g_VS[(size_t)b * 1024 + 512 + k] = s;
    }
}

// ---------------- final matvec: out = VS @ M3 + d3 + A*e3 ----------------
#define FB 16
#define MS 132
__global__ void __launch_bounds__(256) k_final(float* __restrict__ out, int B) {
    extern __shared__ float fsm[];
    float* vs = fsm;               // FB * 1024
    float* mch = fsm + FB * 1024;  // 64 * MS
    int sb = blockIdx.x * FB;
    int tid = threadIdx.x;
    {
        const float4* src = (const float4*)(g_VS + (size_t)sb * 1024);
        float4* dst = (float4*)vs;
        for (int i = tid; i < FB * 256; i += 256) dst[i] = src[i];
    }
    int h = tid & 63, sg = tid >> 6;
    float acc[4] = {0.f, 0.f, 0.f, 0.f};
    const float* vsr0 = vs + (sg * 4 + 0) * 1024;
    const float* vsr1 = vs + (sg * 4 + 1) * 1024;
    const float* vsr2 = vs + (sg * 4 + 2) * 1024;
    const float* vsr3 = vs + (sg * 4 + 3) * 1024;
    for (int kc = 0; kc < 1024; kc += 128) {
        __syncthreads();
        for (int i = tid; i < 64 * 32; i += 256) {
            int r = i >> 5, c = i & 31;
            float4 v = *(const float4*)(g_M3T + r * 1040 + kc + c * 4);
            *(float4*)(mch + r * MS + c * 4) = v;
        }
        __syncthreads();
#pragma unroll 8
        for (int kk = 0; kk < 128; kk += 4) {
            float4 m = *(const float4*)(mch + h * MS + kk);
            float4 a0 = *(const float4*)(vsr0 + kc + kk);
            float4 a1 = *(const float4*)(vsr1 + kc + kk);
            float4 a2 = *(const float4*)(vsr2 + kc + kk);
            float4 a3 = *(const float4*)(vsr3 + kc + kk);
            acc[0] += a0.x * m.x + a0.y * m.y + a0.z * m.z + a0.w * m.w;
            acc[1] += a1.x * m.x + a1.y * m.y + a1.z * m.z + a1.w * m.w;
            acc[2] += a2.x * m.x + a2.y * m.y + a2.z * m.z + a2.w * m.w;
            acc[3] += a3.x * m.x + a3.y * m.y + a3.z * m.z + a3.w * m.w;
        }
    }
    float d3 = g_d3[h], e3 = g_e3[h];
#pragma unroll
    for (int i = 0; i < 4; i++) {
        int b = sb + sg * 4 + i;
        if (b < B) out[(size_t)b * Hq + h] = acc[i] + d3 + g_A[b] * e3;
    }
}

// ---------------- launch ----------------
extern "C" void kernel_launch(void* const* d_in, const int* in_sizes, int n_in,
                              void* d_out, int out_size) {
    const float* hidden = (const float*)d_in[0];
    const float* Wg = (const float*)d_in[1];
    const float* bg = (const float*)d_in[2];
    const float* W1 = (const float*)d_in[3];
    const float* b1 = (const float*)d_in[4];
    const float* W2 = (const float*)d_in[5];
    const float* b2 = (const float*)d_in[6];
    const float* Wq = (const float*)d_in[7];
    const float* bq = (const float*)d_in[8];
    const float* W3 = (const float*)d_in[9];
    const float* b3 = (const float*)d_in[10];
    const int* eidx = (const int*)d_in[11];
    const int* batch = (const int*)d_in[12];
    const int* sidx = (const int*)d_in[13];
    const int* seql = (const int*)d_in[14];

    int N = in_sizes[0] / Dq;
    int B = in_sizes[14];
    int E = in_sizes[11] / 2;
    float* out = (float*)d_out;

    k_mark<<<(N + 255) / 256, 256>>>(batch, N);
    k_scan<<<1, 1024>>>(seql, B, N);
    dim3 gm(Dq / 8, 4);
    k_mats<<<gm, 256>>>(Wg, W1, W2, W3);
    k_vecs<<<Hq, 128>>>(bg, b1, b2, b3, W1, W2, W3);

    cudaFuncSetAttribute(k_main, cudaFuncAttributeMaxDynamicSharedMemorySize,
                         (int)sizeof(SmemS));
    k_main<<<B, NTH, sizeof(SmemS)>>>(hidden, Wq, bq, eidx, sidx, seql, E, B);

    int fsmem = (FB * 1024 + 64 * MS) * (int)sizeof(float);
    cudaFuncSetAttribute(k_final, cudaFuncAttributeMaxDynamicSharedMemorySize, fsmem);
    k_final<<<(B + FB - 1) / FB, 256, fsmem>>>(out, B);
}

// round 13
// speedup vs baseline: 1.5974x; 1.1286x over previous
#include <cuda_runtime.h>
#include <cuda_bf16.h>
#include <cstdint>

#define Dq 512
#define Hq 64
#define NN 40
#define EMAX 104
#define BMAX 8192
#define AST 42
#define NTH 256

// ---------------- device scratch ----------------
__device__ float g_MF[Dq * 256];                 // fused [k][n]: 0:64 M2 | 64:128 M1 | 128:192 M3a | 192:256 M3b
__device__ __nv_bfloat16 g_MBh[256 * Dq];        // B [n][k] hi
__device__ __nv_bfloat16 g_MBl[256 * Dq];        // B [n][k] lo
__device__ float g_Y[(size_t)BMAX * NN * 256];   // hidden @ MF
__device__ float g_c[Hq];
__device__ float g_d3[Hq];
__device__ float g_e3[Hq];
__device__ int g_node_off[BMAX + 1];
__device__ int g_tok_off[BMAX + 1];

__device__ __forceinline__ uint32_t smem_u32(const void* p) {
    uint32_t a;
    asm("{ .reg .u64 t; cvta.to.shared.u64 t, %1; cvt.u32.u64 %0, t; }" : "=r"(a) : "l"(p));
    return a;
}
#define LDSM4(r, addr) \
    asm volatile("ldmatrix.sync.aligned.m8n8.x4.shared.b16 {%0,%1,%2,%3}, [%4];" \
        : "=r"((r)[0]), "=r"((r)[1]), "=r"((r)[2]), "=r"((r)[3]) : "r"(addr))
#define MMA_BF16(c, a, b0_, b1_) \
    asm volatile("mma.sync.aligned.m16n8k16.row.col.f32.bf16.bf16.f32 " \
        "{%0,%1,%2,%3}, {%4,%5,%6,%7}, {%8,%9}, {%0,%1,%2,%3};" \
        : "+f"((c)[0]), "+f"((c)[1]), "+f"((c)[2]), "+f"((c)[3]) \
        : "r"((a)[0]), "r"((a)[1]), "r"((a)[2]), "r"((a)[3]), "r"(b0_), "r"(b1_))
#define CPA16(d, s) \
    asm volatile("cp.async.cg.shared.global [%0], [%1], 16;" :: "r"(d), "l"(s))

// smem buffer layout (per stage, stage stride 40960B)
#define AH_OFF 0
#define AL_OFF 10240
#define BH_OFF 20480
#define BL_OFF 30720
#define STG_STRIDE 40960
#define GSM_TOTAL 81920

// ---------------- prelude ----------------
__global__ void k_mark(const int* __restrict__ batch, int N) {
    int i = blockIdx.x * blockDim.x + threadIdx.x;
    if (i < N) {
        if (i == 0 || batch[i] != batch[i - 1]) g_node_off[batch[i]] = i;
    }
}

__global__ void k_scan(const int* __restrict__ seq_len, int B, int N) {
    __shared__ int wsum[32];
    __shared__ int carry_s;
    if (threadIdx.x == 0) { carry_s = 0; g_node_off[B] = N; }
    __syncthreads();
    for (int base = 0; base < B; base += 1024) {
        int i = base + (int)threadIdx.x;
        int v = (i < B) ? seq_len[i] : 0;
        int lane = threadIdx.x & 31, w = threadIdx.x >> 5;
        int x = v;
        for (int o = 1; o < 32; o <<= 1) {
            int y = __shfl_up_sync(0xffffffffu, x, o);
            if (lane >= o) x += y;
        }
        if (lane == 31) wsum[w] = x;
        __syncthreads();
        if (w == 0) {
            int s = wsum[lane];
            for (int o = 1; o < 32; o <<= 1) {
                int y = __shfl_up_sync(0xffffffffu, s, o);
                if (lane >= o) s += y;
            }
            wsum[lane] = s;
        }
        __syncthreads();
        int excl = x - v + (w ? wsum[w - 1] : 0) + carry_s;
        if (i < B) g_tok_off[i] = excl;
        __syncthreads();
        if (threadIdx.x == 0) carry_s = carry_s + wsum[31];
        __syncthreads();
    }
    if (threadIdx.x == 0) g_tok_off[B] = carry_s;
}

__global__ void k_mats(const float* __restrict__ Wg, const float* __restrict__ W1,
                       const float* __restrict__ W2, const float* __restrict__ W3) {
    __shared__ float wg8[8 * Dq];
    int kb = blockIdx.x;
    int m = blockIdx.y;
    const float* W;
    int blk;
    if (m == 0)      { W = W1;           blk = 1; }
    else if (m == 1) { W = W2;           blk = 0; }
    else if (m == 2) { W = W3;           blk = 2; }
    else             { W = W3 + Dq * Hq; blk = 3; }
    for (int i = threadIdx.x; i < 8 * Dq; i += 256) wg8[i] = Wg[kb * 8 * Dq + i];
    __syncthreads();
    int h = threadIdx.x & 63;
    int r0 = threadIdx.x >> 6;
    float a0 = 0.f, a1 = 0.f;
    for (int d = 0; d < Dq; d++) {
        float wv = W[d * Hq + h];
        a0 += wg8[r0 * Dq + d] * wv;
        a1 += wg8[(r0 + 4) * Dq + d] * wv;
    }
    g_MF[(kb * 8 + r0) * 256 + blk * 64 + h] = a0;
    g_MF[(kb * 8 + r0 + 4) * 256 + blk * 64 + h] = a1;
}

__global__ void k_vecs(const float* __restrict__ bg, const float* __restrict__ b1,
                       const float* __restrict__ b2, const float* __restrict__ b3,
                       const float* __restrict__ W1, const float* __restrict__ W2,
                       const float* __restrict__ W3) {
    __shared__ float red[3][128];
    int h = blockIdx.x, t = threadIdx.x;
    float cv = 0.f, dv = 0.f, ev = 0.f;
    for (int d = t; d < Dq; d += 128) {
        float bgv = bg[d];
        cv += bgv * (W1[d * Hq + h] + W2[d * Hq + h]);
        dv += bgv * W3[d * Hq + h];
        ev += bgv * W3[(Dq + d) * Hq + h];
    }
    red[0][t] = cv; red[1][t] = dv; red[2][t] = ev;
    __syncthreads();
    for (int s = 64; s; s >>= 1) {
        if (t < s) {
            red[0][t] += red[0][t + s];
            red[1][t] += red[1][t + s];
            red[2][t] += red[2][t + s];
        }
        __syncthreads();
    }
    if (t == 0) {
        g_c[h] = red[0][0] + b1[h] + b2[h];
        g_d3[h] = red[1][0] + b3[h];
        g_e3[h] = red[2][0];
    }
}

// pack B = MF^T into bf16 hi/lo [n][k]
__global__ void k_packB() {
    int n = blockIdx.x;
    for (int k = threadIdx.x; k < Dq; k += 128) {
        float v = g_MF[k * 256 + n];
        __nv_bfloat16 h = __float2bfloat16(v);
        float r = v - __bfloat162float(h);
        g_MBh[n * Dq + k] = h;
        g_MBl[n * Dq + k] = __float2bfloat16(r);
    }
}

// ---------------- mma.sync GEMM: g_Y = hidden @ MF (split-bf16 x3) ----------------
// CTA tile 128 rows x 128 cols (grid.y selects col-half), K=512 in 16 chunks of 32.
__global__ void __launch_bounds__(256) k_gemm(const float* __restrict__ hidden) {
    extern __shared__ char sm[];
    uint32_t smb = smem_u32(sm);
    int tid = threadIdx.x, wid = tid >> 5, lane = tid & 31;
    int wm = wid & 1, wn = wid >> 1;           // warp tile: 64m x 32n
    size_t row0 = (size_t)blockIdx.x * 128;
    int nb = blockIdx.y;

    const float* Asrc = hidden + row0 * Dq;
    const __nv_bfloat16* Bhsrc = g_MBh + (size_t)(nb * 128) * Dq;
    const __nv_bfloat16* Blsrc = g_MBl + (size_t)(nb * 128) * Dq;

    int arow = tid >> 3, akq = tid & 7;   // A loader: rows arow + it*32, k-quad akq
    int bn = tid >> 2, bkq = tid & 3;     // B loader: n = bn + it*64, k-oct bkq

    float acc[4][4][4];
#pragma unroll
    for (int mi = 0; mi < 4; mi++)
#pragma unroll
        for (int ni = 0; ni < 4; ni++)
#pragma unroll
            for (int q = 0; q < 4; q++) acc[mi][ni][q] = 0.f;

    float4 pa[4];
    // ---- prologue: chunk 0 ----
#pragma unroll
    for (int it = 0; it < 4; it++)
        pa[it] = *(const float4*)(Asrc + (size_t)(arow + it * 32) * Dq + akq * 4);
#pragma unroll
    for (int it = 0; it < 2; it++) {
        int n = bn + it * 64;
        uint32_t d = smb + BH_OFF + n * 80 + bkq * 16;
        CPA16(d, Bhsrc + (size_t)n * Dq + bkq * 8);
        CPA16(d + (BL_OFF - BH_OFF), Blsrc + (size_t)n * Dq + bkq * 8);
    }
    asm volatile("cp.async.commit_group;");
    // store A chunk0 -> stage 0
#pragma unroll
    for (int it = 0; it < 4; it++) {
        float4 v = pa[it];
        __nv_bfloat162 h0 = __floats2bfloat162_rn(v.x, v.y);
        __nv_bfloat162 h1 = __floats2bfloat162_rn(v.z, v.w);
        float2 f0 = __bfloat1622float2(h0), f1 = __bfloat1622float2(h1);
        __nv_bfloat162 l0 = __floats2bfloat162_rn(v.x - f0.x, v.y - f0.y);
        __nv_bfloat162 l1 = __floats2bfloat162_rn(v.z - f1.x, v.w - f1.y);
        int row = arow + it * 32;
        *(uint2*)(sm + AH_OFF + row * 80 + akq * 8) =
            make_uint2(*(uint32_t*)&h0, *(uint32_t*)&h1);
        *(uint2*)(sm + AL_OFF + row * 80 + akq * 8) =
            make_uint2(*(uint32_t*)&l0, *(uint32_t*)&l1);
    }

    for (int ch = 0; ch < 16; ch++) {
        int bb = ch & 1;
        uint32_t bufb = (uint32_t)bb * STG_STRIDE;
        if (ch < 15) {
            int k0 = (ch + 1) * 32;
#pragma unroll
            for (int it = 0; it < 4; it++)
                pa[it] = *(const float4*)(Asrc + (size_t)(arow + it * 32) * Dq + k0 + akq * 4);
        }
        asm volatile("cp.async.wait_group 0;");
        __syncthreads();
        // issue next B cp.async (into other stage) after sync — no readers there now
        if (ch < 15) {
            int k0 = (ch + 1) * 32;
            uint32_t ob = (uint32_t)(bb ^ 1) * STG_STRIDE;
#pragma unroll
            for (int it = 0; it < 2; it++) {
                int n = bn + it * 64;
                uint32_t d = smb + ob + BH_OFF + n * 80 + bkq * 16;
                CPA16(d, Bhsrc + (size_t)n * Dq + k0 + bkq * 8);
                CPA16(d + (BL_OFF - BH_OFF), Blsrc + (size_t)n * Dq + k0 + bkq * 8);
            }
            asm volatile("cp.async.commit_group;");
        }
        // ---- mma on stage bb ----
        uint32_t aaddr = smb + bufb + AH_OFF +
                         (uint32_t)((wm * 64 + (lane & 15)) * 80 + ((lane >> 4) * 8) * 2);
        uint32_t baddr = smb + bufb + BH_OFF +
                         (uint32_t)((wn * 32 + (lane & 7) + ((lane >> 4) << 3)) * 80 +
                                    (((lane >> 3) & 1) * 8) * 2);
#pragma unroll
        for (int ks = 0; ks < 2; ks++) {
            uint32_t a[4][4], bh[2][4], bl[2][4];
#pragma unroll
            for (int mi = 0; mi < 4; mi++) LDSM4(a[mi], aaddr + mi * 1280 + ks * 32);
#pragma unroll
            for (int np = 0; np < 2; np++) LDSM4(bh[np], baddr + np * 1280 + ks * 32);
#pragma unroll
            for (int np = 0; np < 2; np++) LDSM4(bl[np], baddr + 10240 + np * 1280 + ks * 32);
#pragma unroll
            for (int mi = 0; mi < 4; mi++)
#pragma unroll
                for (int ni = 0; ni < 4; ni++) {
                    int np = ni >> 1, hf = ni & 1;
                    MMA_BF16(acc[mi][ni], a[mi], bh[np][hf * 2], bh[np][hf * 2 + 1]);
                    MMA_BF16(acc[mi][ni], a[mi], bl[np][hf * 2], bl[np][hf * 2 + 1]);
                }
            // A-lo pass (reuse bh)
#pragma unroll
            for (int mi = 0; mi < 4; mi++) LDSM4(a[mi], aaddr + 10240 + mi * 1280 + ks * 32);
#pragma unroll
            for (int mi = 0; mi < 4; mi++)
#pragma unroll
                for (int ni = 0; ni < 4; ni++) {
                    int np = ni >> 1, hf = ni & 1;
                    MMA_BF16(acc[mi][ni], a[mi], bh[np][hf * 2], bh[np][hf * 2 + 1]);
                }
        }
        // store prefetched A into other stage
        if (ch < 15) {
            char* ob = sm + (bb ^ 1) * STG_STRIDE;
#pragma unroll
            for (int it = 0; it < 4; it++) {
                float4 v = pa[it];
                __nv_bfloat162 h0 = __floats2bfloat162_rn(v.x, v.y);
                __nv_bfloat162 h1 = __floats2bfloat162_rn(v.z, v.w);
                float2 f0 = __bfloat1622float2(h0), f1 = __bfloat1622float2(h1);
                __nv_bfloat162 l0 = __floats2bfloat162_rn(v.x - f0.x, v.y - f0.y);
                __nv_bfloat162 l1 = __floats2bfloat162_rn(v.z - f1.x, v.w - f1.y);
                int row = arow + it * 32;
                *(uint2*)(ob + AH_OFF + row * 80 + akq * 8) =
                    make_uint2(*(uint32_t*)&h0, *(uint32_t*)&h1);
                *(uint2*)(ob + AL_OFF + row * 80 + akq * 8) =
                    make_uint2(*(uint32_t*)&l0, *(uint32_t*)&l1);
            }
        }
    }
    // ---- epilogue ----
    int g = lane >> 2, t = lane & 3;
#pragma unroll
    for (int mi = 0; mi < 4; mi++)
#pragma unroll
        for (int ni = 0; ni < 4; ni++) {
            size_t r = row0 + wm * 64 + mi * 16 + g;
            int col = nb * 128 + wn * 32 + ni * 8 + t * 2;
            *(float2*)&g_Y[r * 256 + col] = make_float2(acc[mi][ni][0], acc[mi][ni][1]);
            *(float2*)&g_Y[(r + 8) * 256 + col] = make_float2(acc[mi][ni][2], acc[mi][ni][3]);
        }
}

// ---------------- per-session glue (Y-space) ----------------
struct __align__(16) SmemS {
    float Y2s[NN * 64];
    float A[NN * AST];
    float A2[NN * AST];
    float scr[256];
    float u[Hq];
    float ew[EMAX];
    float dinv[NN];
    float af[NN];
    float w[NN];
    float Atot;
    int es[EMAX], ed[EMAX];
    int deg[NN], cnt[NN], act[NN];
    int nact, jlast, lastnode;
};

__global__ void __launch_bounds__(NTH, 6) k_sess(
    const float* __restrict__ Wq, const float* __restrict__ bq,
    const int* __restrict__ eidx, const int* __restrict__ sidx,
    const int* __restrict__ seq_len, float* __restrict__ out, int E, int B) {
    __shared__ SmemS S;
    int b = blockIdx.x, tid = threadIdx.x;
    int nbase = g_node_off[b];
    int nn = g_node_off[b + 1] - nbase;
    int eps = E / B;
    int ne = eps + nn;
    int tbase = g_tok_off[b];
    int sl = seq_len[b];

    if (tid < NN) { S.deg[tid] = 0; S.cnt[tid] = 0; }
    for (int i = tid; i < NN * AST; i += NTH) S.A[i] = 0.f;
    for (int idx = tid; idx < NN * 16; idx += NTH) {
        int r = idx >> 4, q = idx & 15;
        float4 v = (r < nn)
            ? *(const float4*)(g_Y + (size_t)(nbase + r) * 256 + q * 4)
            : make_float4(0.f, 0.f, 0.f, 0.f);
        *(float4*)&S.Y2s[r * 64 + q * 4] = v;
    }
    for (int e = tid; e < ne; e += NTH) {
        int s, d;
        if (e < eps) {
            s = eidx[(size_t)b * eps + e] - nbase;
            d = eidx[(size_t)E + (size_t)b * eps + e] - nbase;
        } else {
            s = d = e - eps;
        }
        S.es[e] = s; S.ed[e] = d;
    }
    if (tid == 0) S.lastnode = sidx[tbase + sl - 1];
    __syncthreads();
    for (int e = tid; e < ne; e += NTH) atomicAdd(&S.deg[S.ed[e]], 1);
    for (int t = tid; t < sl; t += NTH) atomicAdd(&S.cnt[sidx[tbase + t]], 1);
    __syncthreads();
    if (tid < nn) S.dinv[tid] = rsqrtf((float)S.deg[tid]);
    __syncthreads();
    for (int e = tid; e < ne; e += NTH)
        S.ew[e] = S.dinv[S.es[e]] * S.dinv[S.ed[e]];
    if (tid == 64) {
        int ln = S.lastnode;
        int na = 0, jl = 0;
        for (int n2 = 0; n2 < nn; n2++)
            if (S.cnt[n2] > 0) {
                if (n2 == ln) jl = na;
                S.act[na++] = n2;
            }
        S.nact = na;
        S.jlast = jl;
    }
    __syncthreads();
    if (tid < nn) {
        float* Arow = S.A + tid * AST;
        for (int e = 0; e < ne; e++)
            if (S.ed[e] == tid) Arow[S.es[e]] += S.ew[e];
    }
    __syncthreads();
    int nact = S.nact, jlast = S.jlast;
    for (int c = tid; c < nact * NN; c += NTH) {
        int j = c / NN, rc = c - j * NN;
        const float* Aj = S.A + S.act[j] * AST;
        float s = 0.f;
#pragma unroll 8
        for (int r = 0; r < NN; r++) s += Aj[r] * S.A[r * AST + rc];
        S.A2[j * AST + rc] = s;
    }
    __syncthreads();
    // u[h] = c[h] + A2[jlast] @ Y1 (cols 64..127)
    {
        int h = tid & 63, rg = tid >> 6;
        const float* a2 = S.A2 + jlast * AST;
        float s = 0.f;
        for (int r = rg; r < nn; r += 4)
            s += a2[r] * g_Y[(size_t)(nbase + r) * 256 + 64 + h];
        S.scr[rg * 64 + h] = s;
    }
    __syncthreads();
    if (tid < Hq) {
        float s = g_c[tid];
#pragma unroll
        for (int rg = 0; rg < 4; rg++) s += S.scr[rg * 64 + tid];
        S.u[tid] = s;
    }
    __syncthreads();
    // alpha per active node
    {
        int lane = tid & 31, wp = tid >> 5;
        float bq0 = bq[0];
        float wql = Wq[lane], wqh = Wq[lane + 32];
        float ul = S.u[lane], uh = S.u[lane + 32];
        for (int j = wp; j < nact; j += 8) {
            const float* a2 = S.A2 + j * AST;
            float x1 = ul, x2 = uh;
#pragma unroll 8
            for (int r = 0; r < NN; r++) {
                float av = a2[r];
                x1 += av * S.Y2s[r * 64 + lane];
                x2 += av * S.Y2s[r * 64 + lane + 32];
            }
            float sg = wql / (1.f + __expf(-x1)) + wqh / (1.f + __expf(-x2));
            for (int o = 16; o; o >>= 1) sg += __shfl_xor_sync(0xffffffffu, sg, o);
            if (lane == 0) S.af[j] = (sg + bq0) * (float)S.cnt[S.act[j]];
        }
    }
    __syncthreads();
    if (tid == 0) {
        float A = 0.f;
        for (int j = 0; j < nact; j++) A += S.af[j];
        S.Atot = A;
    }
    if (tid < NN) {
        float s = 0.f;
        for (int j = 0; j < nact; j++) s += S.af[j] * S.A2[j * AST + tid];
        S.w[tid] = s;
    }
    __syncthreads();
    // out = A2[jlast]@Y3a + w@Y3b + d3 + Atot*e3
    {
        int h = tid & 63, rg = tid >> 6;
        const float* a2 = S.A2 + jlast * AST;
        float s = 0.f;
        for (int r = rg; r < nn; r += 4) {
            const float* yr = g_Y + (size_t)(nbase + r) * 256;
            s += a2[r] * yr[128 + h] + S.w[r] * yr[192 + h];
        }
        S.scr[rg * 64 + h] = s;
    }
    __syncthreads();
    if (tid < Hq) {
        float s = g_d3[tid] + S.Atot * g_e3[tid];
#pragma unroll
        for (int rg = 0; rg < 4; rg++) s += S.scr[rg * 64 + tid];
        out[(size_t)b * Hq + tid] = s;
    }
}

// ---------------- launch ----------------
extern "C" void kernel_launch(void* const* d_in, const int* in_sizes, int n_in,
                              void* d_out, int out_size) {
    const float* hidden = (const float*)d_in[0];
    const float* Wg = (const float*)d_in[1];
    const float* bg = (const float*)d_in[2];
    const float* W1 = (const float*)d_in[3];
    const float* b1 = (const float*)d_in[4];
    const float* W2 = (const float*)d_in[5];
    const float* b2 = (const float*)d_in[6];
    const float* Wq = (const float*)d_in[7];
    const float* bq = (const float*)d_in[8];
    const float* W3 = (const float*)d_in[9];
    const float* b3 = (const float*)d_in[10];
    const int* eidx = (const int*)d_in[11];
    const int* batch = (const int*)d_in[12];
    const int* sidx = (const int*)d_in[13];
    const int* seql = (const int*)d_in[14];

    int N = in_sizes[0] / Dq;
    int B = in_sizes[14];
    int E = in_sizes[11] / 2;
    float* out = (float*)d_out;

    k_mark<<<(N + 255) / 256, 256>>>(batch, N);
    k_scan<<<1, 1024>>>(seql, B, N);
    dim3 gm(Dq / 8, 4);
    k_mats<<<gm, 256>>>(Wg, W1, W2, W3);
    k_vecs<<<Hq, 128>>>(bg, b1, b2, b3, W1, W2, W3);
    k_packB<<<256, 128>>>();

    cudaFuncSetAttribute(k_gemm, cudaFuncAttributeMaxDynamicSharedMemorySize, GSM_TOTAL);
    dim3 gg(N / 128, 2);
    k_gemm<<<gg, 256, GSM_TOTAL>>>(hidden);

    k_sess<<<B, NTH>>>(Wq, bq, eidx, sidx, seql, out, E, B);
}

// round 14
// speedup vs baseline: 2.1680x; 1.3572x over previous
#include <cuda_runtime.h>
#include <cuda_bf16.h>
#include <cstdint>

#define Dq 512
#define Hq 64
#define NN 40
#define EMAX 104
#define BMAX 8192
#define AST 42
#define NTH 256

// ---------------- device scratch ----------------
__device__ float g_MG[Dq * 128];                 // [k][n]: 0:64 M2 | 64:128 M3b  (GEMM B)
__device__ float g_MU[Dq * 128];                 // [k][n]: 0:64 M1 | 64:128 M3a  (zu matrix)
__device__ __nv_bfloat16 g_MBh[128 * Dq];        // B [n][k] hi
__device__ __nv_bfloat16 g_MBl[128 * Dq];        // B [n][k] lo
__device__ float g_Y[(size_t)BMAX * NN * 128];   // [X@M2 | X@M3b]
__device__ float g_Z[(size_t)BMAX * Dq];         // z per session
__device__ float g_UO[BMAX * 128];               // [u(64) | oz(64)] per session
__device__ float g_A2g[(size_t)BMAX * 1600];     // A2act rows [b][j][r]
__device__ float g_cnta[BMAX * NN];              // cnt of act[j]
__device__ int g_nact[BMAX];
__device__ float g_c[Hq];
__device__ float g_d3[Hq];
__device__ float g_e3[Hq];
__device__ int g_node_off[BMAX + 1];
__device__ int g_tok_off[BMAX + 1];

__device__ __forceinline__ uint32_t smem_u32(const void* p) {
    uint32_t a;
    asm("{ .reg .u64 t; cvta.to.shared.u64 t, %1; cvt.u32.u64 %0, t; }" : "=r"(a) : "l"(p));
    return a;
}
#define LDSM4(r, addr) \
    asm volatile("ldmatrix.sync.aligned.m8n8.x4.shared.b16 {%0,%1,%2,%3}, [%4];" \
        : "=r"((r)[0]), "=r"((r)[1]), "=r"((r)[2]), "=r"((r)[3]) : "r"(addr))
#define MMA_BF16(c, a, b0_, b1_) \
    asm volatile("mma.sync.aligned.m16n8k16.row.col.f32.bf16.bf16.f32 " \
        "{%0,%1,%2,%3}, {%4,%5,%6,%7}, {%8,%9}, {%0,%1,%2,%3};" \
        : "+f"((c)[0]), "+f"((c)[1]), "+f"((c)[2]), "+f"((c)[3]) \
        : "r"((a)[0]), "r"((a)[1]), "r"((a)[2]), "r"((a)[3]), "r"(b0_), "r"(b1_))
#define CPA16(d, s) \
    asm volatile("cp.async.cg.shared.global [%0], [%1], 16;" :: "r"(d), "l"(s))

#define AH_OFF 0
#define AL_OFF 10240
#define BH_OFF 20480
#define BL_OFF 30720
#define STG_STRIDE 40960
#define GSM_TOTAL 81920

// ---------------- prelude ----------------
__global__ void k_mark(const int* __restrict__ batch, int N) {
    int i = blockIdx.x * blockDim.x + threadIdx.x;
    if (i < N) {
        if (i == 0 || batch[i] != batch[i - 1]) g_node_off[batch[i]] = i;
    }
}

__global__ void k_scan(const int* __restrict__ seq_len, int B, int N) {
    __shared__ int wsum[32];
    __shared__ int carry_s;
    if (threadIdx.x == 0) { carry_s = 0; g_node_off[B] = N; }
    __syncthreads();
    for (int base = 0; base < B; base += 1024) {
        int i = base + (int)threadIdx.x;
        int v = (i < B) ? seq_len[i] : 0;
        int lane = threadIdx.x & 31, w = threadIdx.x >> 5;
        int x = v;
        for (int o = 1; o < 32; o <<= 1) {
            int y = __shfl_up_sync(0xffffffffu, x, o);
            if (lane >= o) x += y;
        }
        if (lane == 31) wsum[w] = x;
        __syncthreads();
        if (w == 0) {
            int s = wsum[lane];
            for (int o = 1; o < 32; o <<= 1) {
                int y = __shfl_up_sync(0xffffffffu, s, o);
                if (lane >= o) s += y;
            }
            wsum[lane] = s;
        }
        __syncthreads();
        int excl = x - v + (w ? wsum[w - 1] : 0) + carry_s;
        if (i < B) g_tok_off[i] = excl;
        __syncthreads();
        if (threadIdx.x == 0) carry_s = carry_s + wsum[31];
        __syncthreads();
    }
    if (threadIdx.x == 0) g_tok_off[B] = carry_s;
}

__global__ void k_mats(const float* __restrict__ Wg, const float* __restrict__ W1,
                       const float* __restrict__ W2, const float* __restrict__ W3) {
    __shared__ float wg8[8 * Dq];
    int kb = blockIdx.x;
    int m = blockIdx.y;
    const float* W;
    if (m == 0)      W = W1;            // -> MU 0:64   (M1)
    else if (m == 1) W = W2;            // -> MG 0:64   (M2)
    else if (m == 2) W = W3;            // -> MU 64:128 (M3a)
    else             W = W3 + Dq * Hq;  // -> MG 64:128 (M3b)
    for (int i = threadIdx.x; i < 8 * Dq; i += 256) wg8[i] = Wg[kb * 8 * Dq + i];
    __syncthreads();
    int h = threadIdx.x & 63;
    int r0 = threadIdx.x >> 6;
    float a0 = 0.f, a1 = 0.f;
    for (int d = 0; d < Dq; d++) {
        float wv = W[d * Hq + h];
        a0 += wg8[r0 * Dq + d] * wv;
        a1 += wg8[(r0 + 4) * Dq + d] * wv;
    }
    int row0 = kb * 8 + r0, row1 = kb * 8 + r0 + 4;
    int off = (m == 2 || m == 3) ? 64 : 0;
    float* dst = (m == 0 || m == 2) ? g_MU : g_MG;
    dst[row0 * 128 + off + h] = a0;
    dst[row1 * 128 + off + h] = a1;
}

__global__ void k_vecs(const float* __restrict__ bg, const float* __restrict__ b1,
                       const float* __restrict__ b2, const float* __restrict__ b3,
                       const float* __restrict__ W1, const float* __restrict__ W2,
                       const float* __restrict__ W3) {
    __shared__ float red[3][128];
    int h = blockIdx.x, t = threadIdx.x;
    float cv = 0.f, dv = 0.f, ev = 0.f;
    for (int d = t; d < Dq; d += 128) {
        float bgv = bg[d];
        cv += bgv * (W1[d * Hq + h] + W2[d * Hq + h]);
        dv += bgv * W3[d * Hq + h];
        ev += bgv * W3[(Dq + d) * Hq + h];
    }
    red[0][t] = cv; red[1][t] = dv; red[2][t] = ev;
    __syncthreads();
    for (int s = 64; s; s >>= 1) {
        if (t < s) {
            red[0][t] += red[0][t + s];
            red[1][t] += red[1][t + s];
            red[2][t] += red[2][t + s];
        }
        __syncthreads();
    }
    if (t == 0) {
        g_c[h] = red[0][0] + b1[h] + b2[h];
        g_d3[h] = red[1][0] + b3[h];
        g_e3[h] = red[2][0];
    }
}

__global__ void k_packB() {
    int n = blockIdx.x;
    for (int k = threadIdx.x; k < Dq; k += 128) {
        float v = g_MG[k * 128 + n];
        __nv_bfloat16 h = __float2bfloat16(v);
        float r = v - __bfloat162float(h);
        g_MBh[n * Dq + k] = h;
        g_MBl[n * Dq + k] = __float2bfloat16(r);
    }
}

// ---------------- mma.sync GEMM: g_Y = hidden @ [M2|M3b] (split-bf16 x3) ----------------
__global__ void __launch_bounds__(256) k_gemm(const float* __restrict__ hidden) {
    extern __shared__ char sm[];
    uint32_t smb = smem_u32(sm);
    int tid = threadIdx.x, wid = tid >> 5, lane = tid & 31;
    int wm = wid & 1, wn = wid >> 1;  // warp tile 64m x 32n
    size_t row0 = (size_t)blockIdx.x * 128;

    const float* Asrc = hidden + row0 * Dq;
    const __nv_bfloat16* Bhsrc = g_MBh;
    const __nv_bfloat16* Blsrc = g_MBl;

    int arow = tid >> 3, akq = tid & 7;
    int bn = tid >> 2, bkq = tid & 3;

    float acc[4][4][4];
#pragma unroll
    for (int mi = 0; mi < 4; mi++)
#pragma unroll
        for (int ni = 0; ni < 4; ni++)
#pragma unroll
            for (int q = 0; q < 4; q++) acc[mi][ni][q] = 0.f;

    float4 pa[4];
#pragma unroll
    for (int it = 0; it < 4; it++)
        pa[it] = *(const float4*)(Asrc + (size_t)(arow + it * 32) * Dq + akq * 4);
#pragma unroll
    for (int it = 0; it < 2; it++) {
        int n = bn + it * 64;
        uint32_t d = smb + BH_OFF + n * 80 + bkq * 16;
        CPA16(d, Bhsrc + (size_t)n * Dq + bkq * 8);
        CPA16(d + (BL_OFF - BH_OFF), Blsrc + (size_t)n * Dq + bkq * 8);
    }
    asm volatile("cp.async.commit_group;");
#pragma unroll
    for (int it = 0; it < 4; it++) {
        float4 v = pa[it];
        __nv_bfloat162 h0 = __floats2bfloat162_rn(v.x, v.y);
        __nv_bfloat162 h1 = __floats2bfloat162_rn(v.z, v.w);
        float2 f0 = __bfloat1622float2(h0), f1 = __bfloat1622float2(h1);
        __nv_bfloat162 l0 = __floats2bfloat162_rn(v.x - f0.x, v.y - f0.y);
        __nv_bfloat162 l1 = __floats2bfloat162_rn(v.z - f1.x, v.w - f1.y);
        int row = arow + it * 32;
        *(uint2*)(sm + AH_OFF + row * 80 + akq * 8) =
            make_uint2(*(uint32_t*)&h0, *(uint32_t*)&h1);
        *(uint2*)(sm + AL_OFF + row * 80 + akq * 8) =
            make_uint2(*(uint32_t*)&l0, *(uint32_t*)&l1);
    }

    for (int ch = 0; ch < 16; ch++) {
        int bb = ch & 1;
        uint32_t bufb = (uint32_t)bb * STG_STRIDE;
        if (ch < 15) {
            int k0 = (ch + 1) * 32;
#pragma unroll
            for (int it = 0; it < 4; it++)
                pa[it] = *(const float4*)(Asrc + (size_t)(arow + it * 32) * Dq + k0 + akq * 4);
        }
        asm volatile("cp.async.wait_group 0;");
        __syncthreads();
        if (ch < 15) {
            int k0 = (ch + 1) * 32;
            uint32_t ob = (uint32_t)(bb ^ 1) * STG_STRIDE;
#pragma unroll
            for (int it = 0; it < 2; it++) {
                int n = bn + it * 64;
                uint32_t d = smb + ob + BH_OFF + n * 80 + bkq * 16;
                CPA16(d, Bhsrc + (size_t)n * Dq + k0 + bkq * 8);
                CPA16(d + (BL_OFF - BH_OFF), Blsrc + (size_t)n * Dq + k0 + bkq * 8);
            }
            asm volatile("cp.async.commit_group;");
        }
        uint32_t aaddr = smb + bufb + AH_OFF +
                         (uint32_t)((wm * 64 + (lane & 15)) * 80 + ((lane >> 4) * 8) * 2);
        uint32_t baddr = smb + bufb + BH_OFF +
                         (uint32_t)((wn * 32 + (lane & 7) + ((lane >> 4) << 3)) * 80 +
                                    (((lane >> 3) & 1) * 8) * 2);
#pragma unroll
        for (int ks = 0; ks < 2; ks++) {
            uint32_t a[4][4], bh[2][4], bl[2][4];
#pragma unroll
            for (int mi = 0; mi < 4; mi++) LDSM4(a[mi], aaddr + mi * 1280 + ks * 32);
#pragma unroll
            for (int np = 0; np < 2; np++) LDSM4(bh[np], baddr + np * 1280 + ks * 32);
#pragma unroll
            for (int np = 0; np < 2; np++) LDSM4(bl[np], baddr + 10240 + np * 1280 + ks * 32);
#pragma unroll
            for (int mi = 0; mi < 4; mi++)
#pragma unroll
                for (int ni = 0; ni < 4; ni++) {
                    int np = ni >> 1, hf = ni & 1;
                    MMA_BF16(acc[mi][ni], a[mi], bh[np][hf * 2], bh[np][hf * 2 + 1]);
                    MMA_BF16(acc[mi][ni], a[mi], bl[np][hf * 2], bl[np][hf * 2 + 1]);
                }
#pragma unroll
            for (int mi = 0; mi < 4; mi++) LDSM4(a[mi], aaddr + 10240 + mi * 1280 + ks * 32);
#pragma unroll
            for (int mi = 0; mi < 4; mi++)
#pragma unroll
                for (int ni = 0; ni < 4; ni++) {
                    int np = ni >> 1, hf = ni & 1;
                    MMA_BF16(acc[mi][ni], a[mi], bh[np][hf * 2], bh[np][hf * 2 + 1]);
                }
        }
        if (ch < 15) {
            char* ob = sm + (bb ^ 1) * STG_STRIDE;
#pragma unroll
            for (int it = 0; it < 4; it++) {
                float4 v = pa[it];
                __nv_bfloat162 h0 = __floats2bfloat162_rn(v.x, v.y);
                __nv_bfloat162 h1 = __floats2bfloat162_rn(v.z, v.w);
                float2 f0 = __bfloat1622float2(h0), f1 = __bfloat1622float2(h1);
                __nv_bfloat162 l0 = __floats2bfloat162_rn(v.x - f0.x, v.y - f0.y);
                __nv_bfloat162 l1 = __floats2bfloat162_rn(v.z - f1.x, v.w - f1.y);
                int row = arow + it * 32;
                *(uint2*)(ob + AH_OFF + row * 80 + akq * 8) =
                    make_uint2(*(uint32_t*)&h0, *(uint32_t*)&h1);
                *(uint2*)(ob + AL_OFF + row * 80 + akq * 8) =
                    make_uint2(*(uint32_t*)&l0, *(uint32_t*)&l1);
            }
        }
    }
    int g = lane >> 2, t = lane & 3;
#pragma unroll
    for (int mi = 0; mi < 4; mi++)
#pragma unroll
        for (int ni = 0; ni < 4; ni++) {
            size_t r = row0 + wm * 64 + mi * 16 + g;
            int col = wn * 32 + ni * 8 + t * 2;
            *(float2*)&g_Y[r * 128 + col] = make_float2(acc[mi][ni][0], acc[mi][ni][1]);
            *(float2*)&g_Y[(r + 8) * 128 + col] = make_float2(acc[mi][ni][2], acc[mi][ni][3]);
        }
}

// ---------------- sessA: graph build + A2 + z ----------------
struct __align__(16) SmemA {
    float A[NN * AST];
    float A2[NN * AST];
    float ew[EMAX];
    float dinv[NN];
    int es[EMAX], ed[EMAX];
    int deg[NN], cnt[NN], act[NN];
    int nact, jlast, lastnode;
};

__global__ void __launch_bounds__(NTH, 6) k_sessA(
    const float* __restrict__ hidden, const int* __restrict__ eidx,
    const int* __restrict__ sidx, const int* __restrict__ seq_len, int E, int B) {
    __shared__ SmemA S;
    int b = blockIdx.x, tid = threadIdx.x;
    int nbase = g_node_off[b];
    int nn = g_node_off[b + 1] - nbase;
    int eps = E / B;
    int ne = eps + nn;
    int tbase = g_tok_off[b];
    int sl = seq_len[b];

    if (tid < NN) { S.deg[tid] = 0; S.cnt[tid] = 0; }
    for (int i = tid; i < NN * AST; i += NTH) S.A[i] = 0.f;
    for (int e = tid; e < ne; e += NTH) {
        int s, d;
        if (e < eps) {
            s = eidx[(size_t)b * eps + e] - nbase;
            d = eidx[(size_t)E + (size_t)b * eps + e] - nbase;
        } else {
            s = d = e - eps;
        }
        S.es[e] = s; S.ed[e] = d;
    }
    if (tid == 0) S.lastnode = sidx[tbase + sl - 1];
    __syncthreads();
    for (int e = tid; e < ne; e += NTH) atomicAdd(&S.deg[S.ed[e]], 1);
    for (int t = tid; t < sl; t += NTH) atomicAdd(&S.cnt[sidx[tbase + t]], 1);
    __syncthreads();
    if (tid < nn) S.dinv[tid] = rsqrtf((float)S.deg[tid]);
    __syncthreads();
    for (int e = tid; e < ne; e += NTH)
        S.ew[e] = S.dinv[S.es[e]] * S.dinv[S.ed[e]];
    if (tid == 64) {
        int ln = S.lastnode;
        int na = 0, jl = 0;
        for (int n2 = 0; n2 < nn; n2++)
            if (S.cnt[n2] > 0) {
                if (n2 == ln) jl = na;
                S.act[na++] = n2;
            }
        S.nact = na;
        S.jlast = jl;
        g_nact[b] = na;
    }
    __syncthreads();
    if (tid < nn) {
        float* Arow = S.A + tid * AST;
        for (int e = 0; e < ne; e++)
            if (S.ed[e] == tid) Arow[S.es[e]] += S.ew[e];
    }
    if (tid >= 128 && tid - 128 < S.nact)
        g_cnta[b * NN + (tid - 128)] = (float)S.cnt[S.act[tid - 128]];
    __syncthreads();
    int nact = S.nact, jlast = S.jlast;
    // A2act rows -> smem + global
    for (int c = tid; c < nact * NN; c += NTH) {
        int j = c / NN, rc = c - j * NN;
        const float* Aj = S.A + S.act[j] * AST;
        float s = 0.f;
#pragma unroll 8
        for (int r = 0; r < NN; r++) s += Aj[r] * S.A[r * AST + rc];
        S.A2[j * AST + rc] = s;
        g_A2g[(size_t)b * 1600 + j * NN + rc] = s;
    }
    __syncthreads();
    // z = A2[jlast] @ X
    {
        const float* a2 = S.A2 + jlast * AST;
        for (int k = tid; k < Dq; k += NTH) {
            float s = 0.f;
#pragma unroll 8
            for (int r = 0; r < nn; r++)
                s += a2[r] * hidden[(size_t)(nbase + r) * Dq + k];
            g_Z[(size_t)b * Dq + k] = s;
        }
    }
}

// ---------------- zu: [u|oz] = Z @ [M1|M3a] + [c|0] ----------------
#define ZFB 16
__global__ void __launch_bounds__(256) k_zu(int B) {
    extern __shared__ float zsm[];
    float* zs = zsm;                 // ZFB*512
    float* mch = zsm + ZFB * 512;    // 128*132
    int sb = blockIdx.x * ZFB;
    int tid = threadIdx.x;
    {
        const float4* src = (const float4*)(g_Z + (size_t)sb * Dq);
        float4* dst = (float4*)zs;
        for (int i = tid; i < ZFB * 128; i += 256) dst[i] = src[i];
    }
    int h = tid & 127, sg = tid >> 7;
    float acc[8];
#pragma unroll
    for (int i = 0; i < 8; i++) acc[i] = 0.f;
    for (int kc = 0; kc < Dq; kc += 128) {
        __syncthreads();
        for (int i = tid; i < 128 * 32; i += 256) {
            int r = i >> 5, c = i & 31;
            float4 v = *(const float4*)(g_MU + (size_t)(kc + r) * 128 + c * 4);
            *(float4*)(mch + r * 132 + c * 4) = v;
        }
        __syncthreads();
#pragma unroll 4
        for (int kk = 0; kk < 128; kk++) {
            float m = mch[kk * 132 + h];
#pragma unroll
            for (int i = 0; i < 8; i++)
                acc[i] += zs[(sg * 8 + i) * Dq + kc + kk] * m;
        }
    }
    float cadd = (h < 64) ? g_c[h] : 0.f;
#pragma unroll
    for (int i = 0; i < 8; i++) {
        int b = sb + sg * 8 + i;
        if (b < B) g_UO[b * 128 + h] = acc[i] + cadd;
    }
}

// ---------------- sessB: alpha + output ----------------
struct __align__(16) SmemB {
    float Ys[NN * 128];
    float A2s[NN * NN];
    float scr[256];
    float u[Hq];
    float af[NN];
    float w[NN];
    float cnta[NN];
    float Atot;
};

__global__ void __launch_bounds__(NTH, 6) k_sessB(
    const float* __restrict__ Wq, const float* __restrict__ bq,
    float* __restrict__ out, int B) {
    __shared__ SmemB S;
    int b = blockIdx.x, tid = threadIdx.x;
    int nbase = g_node_off[b];
    int nn = g_node_off[b + 1] - nbase;
    int nact = g_nact[b];

    for (int idx = tid; idx < NN * 32; idx += NTH) {
        int r = idx >> 5, q = idx & 31;
        float4 v = (r < nn)
            ? *(const float4*)(g_Y + (size_t)(nbase + r) * 128 + q * 4)
            : make_float4(0.f, 0.f, 0.f, 0.f);
        *(float4*)&S.Ys[r * 128 + q * 4] = v;
    }
    for (int i = tid; i < nact * NN; i += NTH)
        S.A2s[i] = g_A2g[(size_t)b * 1600 + i];
    if (tid < Hq) S.u[tid] = g_UO[b * 128 + tid];
    if (tid >= 64 && tid < 64 + NN) S.cnta[tid - 64] = g_cnta[b * NN + (tid - 64)];
    __syncthreads();
    // alpha per active node
    {
        int lane = tid & 31, wp = tid >> 5;
        float bq0 = bq[0];
        float wql = Wq[lane], wqh = Wq[lane + 32];
        float ul = S.u[lane], uh = S.u[lane + 32];
        for (int j = wp; j < nact; j += 8) {
            const float* a2 = S.A2s + j * NN;
            float x1 = ul, x2 = uh;
#pragma unroll 8
            for (int r = 0; r < NN; r++) {
                float av = a2[r];
                x1 += av * S.Ys[r * 128 + lane];
                x2 += av * S.Ys[r * 128 + lane + 32];
            }
            float sg = wql / (1.f + __expf(-x1)) + wqh / (1.f + __expf(-x2));
            for (int o = 16; o; o >>= 1) sg += __shfl_xor_sync(0xffffffffu, sg, o);
            if (lane == 0) S.af[j] = (sg + bq0) * S.cnta[j];
        }
    }
    __syncthreads();
    if (tid == 0) {
        float A = 0.f;
        for (int j = 0; j < nact; j++) A += S.af[j];
        S.Atot = A;
    }
    if (tid < NN) {
        float s = 0.f;
        for (int j = 0; j < nact; j++) s += S.af[j] * S.A2s[j * NN + tid];
        S.w[tid] = s;
    }
    __syncthreads();
    // out = oz + w@Y3b + d3 + Atot*e3
    {
        int h = tid & 63, rg = tid >> 6;
        float s = 0.f;
        for (int r = rg; r < nn; r += 4)
            s += S.w[r] * S.Ys[r * 128 + 64 + h];
        S.scr[rg * 64 + h] = s;
    }
    __syncthreads();
    if (tid < Hq) {
        float s = g_UO[b * 128 + 64 + tid] + g_d3[tid] + S.Atot * g_e3[tid];
#pragma unroll
        for (int rg = 0; rg < 4; rg++) s += S.scr[rg * 64 + tid];
        out[(size_t)b * Hq + tid] = s;
    }
}

// ---------------- launch ----------------
extern "C" void kernel_launch(void* const* d_in, const int* in_sizes, int n_in,
                              void* d_out, int out_size) {
    const float* hidden = (const float*)d_in[0];
    const float* Wg = (const float*)d_in[1];
    const float* bg = (const float*)d_in[2];
    const float* W1 = (const float*)d_in[3];
    const float* b1 = (const float*)d_in[4];
    const float* W2 = (const float*)d_in[5];
    const float* b2 = (const float*)d_in[6];
    const float* Wq = (const float*)d_in[7];
    const float* bq = (const float*)d_in[8];
    const float* W3 = (const float*)d_in[9];
    const float* b3 = (const float*)d_in[10];
    const int* eidx = (const int*)d_in[11];
    const int* batch = (const int*)d_in[12];
    const int* sidx = (const int*)d_in[13];
    const int* seql = (const int*)d_in[14];

    int N = in_sizes[0] / Dq;
    int B = in_sizes[14];
    int E = in_sizes[11] / 2;
    float* out = (float*)d_out;

    k_mark<<<(N + 255) / 256, 256>>>(batch, N);
    k_scan<<<1, 1024>>>(seql, B, N);
    dim3 gm(Dq / 8, 4);
    k_mats<<<gm, 256>>>(Wg, W1, W2, W3);
    k_vecs<<<Hq, 128>>>(bg, b1, b2, b3, W1, W2, W3);
    k_packB<<<128, 128>>>();

    k_sessA<<<B, NTH>>>(hidden, eidx, sidx, seql, E, B);

    int zsm = (ZFB * 512 + 128 * 132) * (int)sizeof(float);
    cudaFuncSetAttribute(k_zu, cudaFuncAttributeMaxDynamicSharedMemorySize, zsm);
    k_zu<<<(B + ZFB - 1) / ZFB, 256, zsm>>>(B);

    cudaFuncSetAttribute(k_gemm, cudaFuncAttributeMaxDynamicSharedMemorySize, GSM_TOTAL);
    k_gemm<<<N / 128, 256, GSM_TOTAL>>>(hidden);

    k_sessB<<<B, NTH>>>(Wq, bq, out, B);
}

// round 15
// speedup vs baseline: 2.1703x; 1.0010x over previous
#include <cuda_runtime.h>
#include <cuda_bf16.h>
#include <cstdint>

#define Dq 512
#define Hq 64
#define NN 40
#define EMAX 104
#define BMAX 8192
#define AST 42
#define NTH 256

// ---------------- device scratch ----------------
__device__ float g_MG[Dq * 64];                  // M2 [k][n]
__device__ float g_MU[Dq * 128];                 // [k][n]: 0:64 M1 | 64:128 M3a
__device__ float g_M3b[Dq * 64];                 // M3b [k][n]
__device__ __nv_bfloat16 g_MBh[64 * Dq];         // B [n][k] hi
__device__ __nv_bfloat16 g_MBl[64 * Dq];         // B [n][k] lo
__device__ float g_Y[(size_t)BMAX * NN * 64];    // X@M2
__device__ float g_Z[(size_t)BMAX * Dq];         // z per session
__device__ float g_SP[(size_t)BMAX * Dq];        // sP per session
__device__ float g_UO[BMAX * 128];               // [u(64) | oz(64)]
__device__ float g_A2g[(size_t)BMAX * 1600];     // A2act rows [b][j][r]
__device__ float g_cnta[BMAX * NN];
__device__ float g_A[BMAX];
__device__ int g_nact[BMAX];
__device__ float g_c[Hq];
__device__ float g_d3[Hq];
__device__ float g_e3[Hq];
__device__ int g_node_off[BMAX + 1];
__device__ int g_tok_off[BMAX + 1];

__device__ __forceinline__ uint32_t smem_u32(const void* p) {
    uint32_t a;
    asm("{ .reg .u64 t; cvta.to.shared.u64 t, %1; cvt.u32.u64 %0, t; }" : "=r"(a) : "l"(p));
    return a;
}
#define LDSM4(r, addr) \
    asm volatile("ldmatrix.sync.aligned.m8n8.x4.shared.b16 {%0,%1,%2,%3}, [%4];" \
        : "=r"((r)[0]), "=r"((r)[1]), "=r"((r)[2]), "=r"((r)[3]) : "r"(addr))
#define MMA_BF16(c, a, b0_, b1_) \
    asm volatile("mma.sync.aligned.m16n8k16.row.col.f32.bf16.bf16.f32 " \
        "{%0,%1,%2,%3}, {%4,%5,%6,%7}, {%8,%9}, {%0,%1,%2,%3};" \
        : "+f"((c)[0]), "+f"((c)[1]), "+f"((c)[2]), "+f"((c)[3]) \
        : "r"((a)[0]), "r"((a)[1]), "r"((a)[2]), "r"((a)[3]), "r"(b0_), "r"(b1_))
#define CPA16(d, s) \
    asm volatile("cp.async.cg.shared.global [%0], [%1], 16;" :: "r"(d), "l"(s))

#define AH_OFF 0
#define AL_OFF 10240
#define BH_OFF 20480
#define BL_OFF 25600
#define STG_STRIDE 30720
#define GSM_TOTAL 61440

// ---------------- prelude ----------------
__global__ void k_mark(const int* __restrict__ batch, int N) {
    int i = blockIdx.x * blockDim.x + threadIdx.x;
    if (i < N) {
        if (i == 0 || batch[i] != batch[i - 1]) g_node_off[batch[i]] = i;
    }
}

__global__ void k_scan(const int* __restrict__ seq_len, int B, int N) {
    __shared__ int wsum[32];
    __shared__ int carry_s;
    if (threadIdx.x == 0) { carry_s = 0; g_node_off[B] = N; }
    __syncthreads();
    for (int base = 0; base < B; base += 1024) {
        int i = base + (int)threadIdx.x;
        int v = (i < B) ? seq_len[i] : 0;
        int lane = threadIdx.x & 31, w = threadIdx.x >> 5;
        int x = v;
        for (int o = 1; o < 32; o <<= 1) {
            int y = __shfl_up_sync(0xffffffffu, x, o);
            if (lane >= o) x += y;
        }
        if (lane == 31) wsum[w] = x;
        __syncthreads();
        if (w == 0) {
            int s = wsum[lane];
            for (int o = 1; o < 32; o <<= 1) {
                int y = __shfl_up_sync(0xffffffffu, s, o);
                if (lane >= o) s += y;
            }
            wsum[lane] = s;
        }
        __syncthreads();
        int excl = x - v + (w ? wsum[w - 1] : 0) + carry_s;
        if (i < B) g_tok_off[i] = excl;
        __syncthreads();
        if (threadIdx.x == 0) carry_s = carry_s + wsum[31];
        __syncthreads();
    }
    if (threadIdx.x == 0) g_tok_off[B] = carry_s;
}

__global__ void k_mats(const float* __restrict__ Wg, const float* __restrict__ W1,
                       const float* __restrict__ W2, const float* __restrict__ W3) {
    __shared__ float wg8[8 * Dq];
    int kb = blockIdx.x;
    int m = blockIdx.y;
    const float* W;
    if (m == 0)      W = W1;            // -> MU 0:64
    else if (m == 1) W = W2;            // -> MG
    else if (m == 2) W = W3;            // -> MU 64:128
    else             W = W3 + Dq * Hq;  // -> M3b
    for (int i = threadIdx.x; i < 8 * Dq; i += 256) wg8[i] = Wg[kb * 8 * Dq + i];
    __syncthreads();
    int h = threadIdx.x & 63;
    int r0 = threadIdx.x >> 6;
    float a0 = 0.f, a1 = 0.f;
    for (int d = 0; d < Dq; d++) {
        float wv = W[d * Hq + h];
        a0 += wg8[r0 * Dq + d] * wv;
        a1 += wg8[(r0 + 4) * Dq + d] * wv;
    }
    int row0 = kb * 8 + r0, row1 = kb * 8 + r0 + 4;
    if (m == 1) {
        g_MG[row0 * 64 + h] = a0; g_MG[row1 * 64 + h] = a1;
    } else if (m == 3) {
        g_M3b[row0 * 64 + h] = a0; g_M3b[row1 * 64 + h] = a1;
    } else {
        int off = (m == 2) ? 64 : 0;
        g_MU[row0 * 128 + off + h] = a0;
        g_MU[row1 * 128 + off + h] = a1;
    }
}

__global__ void k_vecs(const float* __restrict__ bg, const float* __restrict__ b1,
                       const float* __restrict__ b2, const float* __restrict__ b3,
                       const float* __restrict__ W1, const float* __restrict__ W2,
                       const float* __restrict__ W3) {
    __shared__ float red[3][128];
    int h = blockIdx.x, t = threadIdx.x;
    float cv = 0.f, dv = 0.f, ev = 0.f;
    for (int d = t; d < Dq; d += 128) {
        float bgv = bg[d];
        cv += bgv * (W1[d * Hq + h] + W2[d * Hq + h]);
        dv += bgv * W3[d * Hq + h];
        ev += bgv * W3[(Dq + d) * Hq + h];
    }
    red[0][t] = cv; red[1][t] = dv; red[2][t] = ev;
    __syncthreads();
    for (int s = 64; s; s >>= 1) {
        if (t < s) {
            red[0][t] += red[0][t + s];
            red[1][t] += red[1][t + s];
            red[2][t] += red[2][t + s];
        }
        __syncthreads();
    }
    if (t == 0) {
        g_c[h] = red[0][0] + b1[h] + b2[h];
        g_d3[h] = red[1][0] + b3[h];
        g_e3[h] = red[2][0];
    }
}

__global__ void k_packB() {
    int n = blockIdx.x;
    for (int k = threadIdx.x; k < Dq; k += 128) {
        float v = g_MG[k * 64 + n];
        __nv_bfloat16 h = __float2bfloat16(v);
        float r = v - __bfloat162float(h);
        g_MBh[n * Dq + k] = h;
        g_MBl[n * Dq + k] = __float2bfloat16(r);
    }
}

// ---------------- mma.sync GEMM: g_Y = hidden @ M2 (split-bf16 x3) ----------------
__global__ void __launch_bounds__(256) k_gemm(const float* __restrict__ hidden) {
    extern __shared__ char sm[];
    uint32_t smb = smem_u32(sm);
    int tid = threadIdx.x, wid = tid >> 5, lane = tid & 31;
    int wm = wid & 3, wn = wid >> 2;  // warp tile 32m x 32n
    size_t row0 = (size_t)blockIdx.x * 128;

    const float* Asrc = hidden + row0 * Dq;
    int arow = tid >> 3, akq = tid & 7;
    int bn = tid >> 2, bkq = tid & 3;

    float acc[2][4][4];
#pragma unroll
    for (int mi = 0; mi < 2; mi++)
#pragma unroll
        for (int ni = 0; ni < 4; ni++)
#pragma unroll
            for (int q = 0; q < 4; q++) acc[mi][ni][q] = 0.f;

    float4 pa[4];
#pragma unroll
    for (int it = 0; it < 4; it++)
        pa[it] = *(const float4*)(Asrc + (size_t)(arow + it * 32) * Dq + akq * 4);
    {
        uint32_t d = smb + BH_OFF + bn * 80 + bkq * 16;
        CPA16(d, g_MBh + (size_t)bn * Dq + bkq * 8);
        CPA16(d + (BL_OFF - BH_OFF), g_MBl + (size_t)bn * Dq + bkq * 8);
    }
    asm volatile("cp.async.commit_group;");
#pragma unroll
    for (int it = 0; it < 4; it++) {
        float4 v = pa[it];
        __nv_bfloat162 h0 = __floats2bfloat162_rn(v.x, v.y);
        __nv_bfloat162 h1 = __floats2bfloat162_rn(v.z, v.w);
        float2 f0 = __bfloat1622float2(h0), f1 = __bfloat1622float2(h1);
        __nv_bfloat162 l0 = __floats2bfloat162_rn(v.x - f0.x, v.y - f0.y);
        __nv_bfloat162 l1 = __floats2bfloat162_rn(v.z - f1.x, v.w - f1.y);
        int row = arow + it * 32;
        *(uint2*)(sm + AH_OFF + row * 80 + akq * 8) =
            make_uint2(*(uint32_t*)&h0, *(uint32_t*)&h1);
        *(uint2*)(sm + AL_OFF + row * 80 + akq * 8) =
            make_uint2(*(uint32_t*)&l0, *(uint32_t*)&l1);
    }

    for (int ch = 0; ch < 16; ch++) {
        int bb = ch & 1;
        uint32_t bufb = (uint32_t)bb * STG_STRIDE;
        if (ch < 15) {
            int k0 = (ch + 1) * 32;
#pragma unroll
            for (int it = 0; it < 4; it++)
                pa[it] = *(const float4*)(Asrc + (size_t)(arow + it * 32) * Dq + k0 + akq * 4);
        }
        asm volatile("cp.async.wait_group 0;");
        __syncthreads();
        if (ch < 15) {
            int k0 = (ch + 1) * 32;
            uint32_t ob = (uint32_t)(bb ^ 1) * STG_STRIDE;
            uint32_t d = smb + ob + BH_OFF + bn * 80 + bkq * 16;
            CPA16(d, g_MBh + (size_t)bn * Dq + k0 + bkq * 8);
            CPA16(d + (BL_OFF - BH_OFF), g_MBl + (size_t)bn * Dq + k0 + bkq * 8);
            asm volatile("cp.async.commit_group;");
        }
        uint32_t aaddr = smb + bufb + AH_OFF +
                         (uint32_t)((wm * 32 + (lane & 15)) * 80 + ((lane >> 4) * 8) * 2);
        uint32_t baddr = smb + bufb + BH_OFF +
                         (uint32_t)(((lane & 7) + ((lane >> 4) << 3) + wn * 32) * 80 +
                                    (((lane >> 3) & 1) * 8) * 2);
#pragma unroll
        for (int ks = 0; ks < 2; ks++) {
            uint32_t a[2][4], bh[2][4], bl[2][4];
#pragma unroll
            for (int mi = 0; mi < 2; mi++) LDSM4(a[mi], aaddr + mi * 1280 + ks * 32);
#pragma unroll
            for (int np = 0; np < 2; np++) LDSM4(bh[np], baddr + np * 1280 + ks * 32);
#pragma unroll
            for (int np = 0; np < 2; np++) LDSM4(bl[np], baddr + 5120 + np * 1280 + ks * 32);
#pragma unroll
            for (int mi = 0; mi < 2; mi++)
#pragma unroll
                for (int ni = 0; ni < 4; ni++) {
                    int np = ni >> 1, hf = ni & 1;
                    MMA_BF16(acc[mi][ni], a[mi], bh[np][hf * 2], bh[np][hf * 2 + 1]);
                    MMA_BF16(acc[mi][ni], a[mi], bl[np][hf * 2], bl[np][hf * 2 + 1]);
                }
#pragma unroll
            for (int mi = 0; mi < 2; mi++) LDSM4(a[mi], aaddr + 10240 + mi * 1280 + ks * 32);
#pragma unroll
            for (int mi = 0; mi < 2; mi++)
#pragma unroll
                for (int ni = 0; ni < 4; ni++) {
                    int np = ni >> 1, hf = ni & 1;
                    MMA_BF16(acc[mi][ni], a[mi], bh[np][hf * 2], bh[np][hf * 2 + 1]);
                }
        }
        if (ch < 15) {
            char* ob = sm + (bb ^ 1) * STG_STRIDE;
#pragma unroll
            for (int it = 0; it < 4; it++) {
                float4 v = pa[it];
                __nv_bfloat162 h0 = __floats2bfloat162_rn(v.x, v.y);
                __nv_bfloat162 h1 = __floats2bfloat162_rn(v.z, v.w);
                float2 f0 = __bfloat1622float2(h0), f1 = __bfloat1622float2(h1);
                __nv_bfloat162 l0 = __floats2bfloat162_rn(v.x - f0.x, v.y - f0.y);
                __nv_bfloat162 l1 = __floats2bfloat162_rn(v.z - f1.x, v.w - f1.y);
                int row = arow + it * 32;
                *(uint2*)(ob + AH_OFF + row * 80 + akq * 8) =
                    make_uint2(*(uint32_t*)&h0, *(uint32_t*)&h1);
                *(uint2*)(ob + AL_OFF + row * 80 + akq * 8) =
                    make_uint2(*(uint32_t*)&l0, *(uint32_t*)&l1);
            }
        }
    }
    int g = lane >> 2, t = lane & 3;
#pragma unroll
    for (int mi = 0; mi < 2; mi++)
#pragma unroll
        for (int ni = 0; ni < 4; ni++) {
            size_t r = row0 + wm * 32 + mi * 16 + g;
            int col = wn * 32 + ni * 8 + t * 2;
            *(float2*)&g_Y[r * 64 + col] = make_float2(acc[mi][ni][0], acc[mi][ni][1]);
            *(float2*)&g_Y[(r + 8) * 64 + col] = make_float2(acc[mi][ni][2], acc[mi][ni][3]);
        }
}

// ---------------- sessA: graph build + A2 + z ----------------
struct __align__(16) SmemA {
    float A[NN * AST];
    float A2[NN * AST];
    float ew[EMAX];
    float dinv[NN];
    int es[EMAX], ed[EMAX];
    int deg[NN], cnt[NN], act[NN];
    int nact, jlast, lastnode;
};

__global__ void __launch_bounds__(NTH, 6) k_sessA(
    const float* __restrict__ hidden, const int* __restrict__ eidx,
    const int* __restrict__ sidx, const int* __restrict__ seq_len, int E, int B) {
    __shared__ SmemA S;
    int b = blockIdx.x, tid = threadIdx.x;
    int nbase = g_node_off[b];
    int nn = g_node_off[b + 1] - nbase;
    int eps = E / B;
    int ne = eps + nn;
    int tbase = g_tok_off[b];
    int sl = seq_len[b];

    if (tid < NN) { S.deg[tid] = 0; S.cnt[tid] = 0; }
    for (int i = tid; i < NN * AST; i += NTH) S.A[i] = 0.f;
    for (int e = tid; e < ne; e += NTH) {
        int s, d;
        if (e < eps) {
            s = eidx[(size_t)b * eps + e] - nbase;
            d = eidx[(size_t)E + (size_t)b * eps + e] - nbase;
        } else {
            s = d = e - eps;
        }
        S.es[e] = s; S.ed[e] = d;
    }
    if (tid == 0) S.lastnode = sidx[tbase + sl - 1];
    __syncthreads();
    for (int e = tid; e < ne; e += NTH) atomicAdd(&S.deg[S.ed[e]], 1);
    for (int t = tid; t < sl; t += NTH) atomicAdd(&S.cnt[sidx[tbase + t]], 1);
    __syncthreads();
    if (tid < nn) S.dinv[tid] = rsqrtf((float)S.deg[tid]);
    __syncthreads();
    for (int e = tid; e < ne; e += NTH)
        S.ew[e] = S.dinv[S.es[e]] * S.dinv[S.ed[e]];
    if (tid == 64) {
        int ln = S.lastnode;
        int na = 0, jl = 0;
        for (int n2 = 0; n2 < nn; n2++)
            if (S.cnt[n2] > 0) {
                if (n2 == ln) jl = na;
                S.act[na++] = n2;
            }
        S.nact = na;
        S.jlast = jl;
        g_nact[b] = na;
    }
    __syncthreads();
    if (tid < nn) {
        float* Arow = S.A + tid * AST;
        for (int e = 0; e < ne; e++)
            if (S.ed[e] == tid) Arow[S.es[e]] += S.ew[e];
    }
    if (tid >= 128 && tid - 128 < S.nact)
        g_cnta[b * NN + (tid - 128)] = (float)S.cnt[S.act[tid - 128]];
    __syncthreads();
    int nact = S.nact, jlast = S.jlast;
    for (int c = tid; c < nact * NN; c += NTH) {
        int j = c / NN, rc = c - j * NN;
        const float* Aj = S.A + S.act[j] * AST;
        float s = 0.f;
#pragma unroll 8
        for (int r = 0; r < NN; r++) s += Aj[r] * S.A[r * AST + rc];
        S.A2[j * AST + rc] = s;
        g_A2g[(size_t)b * 1600 + j * NN + rc] = s;
    }
    __syncthreads();
    {
        const float* a2 = S.A2 + jlast * AST;
        for (int k = tid; k < Dq; k += NTH) {
            float s = 0.f;
#pragma unroll 8
            for (int r = 0; r < nn; r++)
                s += a2[r] * hidden[(size_t)(nbase + r) * Dq + k];
            g_Z[(size_t)b * Dq + k] = s;
        }
    }
}

// ---------------- zu: [u|oz] = Z @ [M1|M3a] + [c|0] ----------------
#define ZFB 16
__global__ void __launch_bounds__(256) k_zu(int B) {
    extern __shared__ float zsm[];
    float* zs = zsm;                 // ZFB*512
    float* mch = zsm + ZFB * 512;    // 128*132
    int sb = blockIdx.x * ZFB;
    int tid = threadIdx.x;
    {
        const float4* src = (const float4*)(g_Z + (size_t)sb * Dq);
        float4* dst = (float4*)zs;
        for (int i = tid; i < ZFB * 128; i += 256) dst[i] = src[i];
    }
    int h = tid & 127, sg = tid >> 7;
    float acc[8];
#pragma unroll
    for (int i = 0; i < 8; i++) acc[i] = 0.f;
    for (int kc = 0; kc < Dq; kc += 128) {
        __syncthreads();
        for (int i = tid; i < 128 * 32; i += 256) {
            int r = i >> 5, c = i & 31;
            float4 v = *(const float4*)(g_MU + (size_t)(kc + r) * 128 + c * 4);
            *(float4*)(mch + r * 132 + c * 4) = v;
        }
        __syncthreads();
#pragma unroll 4
        for (int kk = 0; kk < 128; kk++) {
            float m = mch[kk * 132 + h];
#pragma unroll
            for (int i = 0; i < 8; i++)
                acc[i] += zs[(sg * 8 + i) * Dq + kc + kk] * m;
        }
    }
    float cadd = (h < 64) ? g_c[h] : 0.f;
#pragma unroll
    for (int i = 0; i < 8; i++) {
        int b = sb + sg * 8 + i;
        if (b < B) g_UO[b * 128 + h] = acc[i] + cadd;
    }
}

// ---------------- sessB: alpha + w + sP ----------------
struct __align__(16) SmemB {
    float Ys[NN * 64];
    float A2s[NN * NN];
    float u[Hq];
    float af[NN];
    float w[NN];
    float cnta[NN];
    float Atot;
};

__global__ void __launch_bounds__(NTH, 6) k_sessB(
    const float* __restrict__ hidden, const float* __restrict__ Wq,
    const float* __restrict__ bq, int B) {
    __shared__ SmemB S;
    int b = blockIdx.x, tid = threadIdx.x;
    int nbase = g_node_off[b];
    int nn = g_node_off[b + 1] - nbase;
    int nact = g_nact[b];

    for (int idx = tid; idx < NN * 16; idx += NTH) {
        int r = idx >> 4, q = idx & 15;
        float4 v = (r < nn)
            ? *(const float4*)(g_Y + (size_t)(nbase + r) * 64 + q * 4)
            : make_float4(0.f, 0.f, 0.f, 0.f);
        *(float4*)&S.Ys[r * 64 + q * 4] = v;
    }
    for (int i = tid; i < nact * NN; i += NTH)
        S.A2s[i] = g_A2g[(size_t)b * 1600 + i];
    if (tid < Hq) S.u[tid] = g_UO[b * 128 + tid];
    if (tid >= 64 && tid < 64 + NN) S.cnta[tid - 64] = g_cnta[b * NN + (tid - 64)];
    __syncthreads();
    {
        int lane = tid & 31, wp = tid >> 5;
        float bq0 = bq[0];
        float wql = Wq[lane], wqh = Wq[lane + 32];
        float ul = S.u[lane], uh = S.u[lane + 32];
        for (int j = wp; j < nact; j += 8) {
            const float* a2 = S.A2s + j * NN;
            float x1 = ul, x2 = uh;
#pragma unroll 8
            for (int r = 0; r < NN; r++) {
                float av = a2[r];
                x1 += av * S.Ys[r * 64 + lane];
                x2 += av * S.Ys[r * 64 + lane + 32];
            }
            float sg = wql / (1.f + __expf(-x1)) + wqh / (1.f + __expf(-x2));
            for (int o = 16; o; o >>= 1) sg += __shfl_xor_sync(0xffffffffu, sg, o);
            if (lane == 0) S.af[j] = (sg + bq0) * S.cnta[j];
        }
    }
    __syncthreads();
    if (tid == 0) {
        float A = 0.f;
        for (int j = 0; j < nact; j++) A += S.af[j];
        S.Atot = A;
        g_A[b] = A;
    }
    if (tid < NN) {
        float s = 0.f;
        for (int j = 0; j < nact; j++) s += S.af[j] * S.A2s[j * NN + tid];
        S.w[tid] = s;
    }
    __syncthreads();
    // sP = w @ X
    for (int k = tid; k < Dq; k += NTH) {
        float s = 0.f;
#pragma unroll 8
        for (int r = 0; r < nn; r++)
            s += S.w[r] * hidden[(size_t)(nbase + r) * Dq + k];
        g_SP[(size_t)b * Dq + k] = s;
    }
}

// ---------------- zu2: out = sP @ M3b + oz + d3 + A*e3 ----------------
__global__ void __launch_bounds__(256) k_zu2(float* __restrict__ out, int B) {
    extern __shared__ float zsm[];
    float* zs = zsm;                 // ZFB*512
    float* mch = zsm + ZFB * 512;    // 128*68
    int sb = blockIdx.x * ZFB;
    int tid = threadIdx.x;
    {
        const float4* src = (const float4*)(g_SP + (size_t)sb * Dq);
        float4* dst = (float4*)zs;
        for (int i = tid; i < ZFB * 128; i += 256) dst[i] = src[i];
    }
    int h = tid & 63, sg = tid >> 6;
    float acc[4];
#pragma unroll
    for (int i = 0; i < 4; i++) acc[i] = 0.f;
    for (int kc = 0; kc < Dq; kc += 128) {
        __syncthreads();
        for (int i = tid; i < 128 * 16; i += 256) {
            int r = i >> 4, c = i & 15;
            float4 v = *(const float4*)(g_M3b + (size_t)(kc + r) * 64 + c * 4);
            *(float4*)(mch + r * 68 + c * 4) = v;
        }
        __syncthreads();
#pragma unroll 4
        for (int kk = 0; kk < 128; kk++) {
            float m = mch[kk * 68 + h];
#pragma unroll
            for (int i = 0; i < 4; i++)
                acc[i] += zs[(sg * 4 + i) * Dq + kc + kk] * m;
        }
    }
#pragma unroll
    for (int i = 0; i < 4; i++) {
        int b = sb + sg * 4 + i;
        if (b < B)
            out[(size_t)b * Hq + h] =
                acc[i] + g_UO[b * 128 + 64 + h] + g_d3[h] + g_A[b] * g_e3[h];
    }
}

// ---------------- launch ----------------
extern "C" void kernel_launch(void* const* d_in, const int* in_sizes, int n_in,
                              void* d_out, int out_size) {
    const float* hidden = (const float*)d_in[0];
    const float* Wg = (const float*)d_in[1];
    const float* bg = (const float*)d_in[2];
    const float* W1 = (const float*)d_in[3];
    const float* b1 = (const float*)d_in[4];
    const float* W2 = (const float*)d_in[5];
    const float* b2 = (const float*)d_in[6];
    const float* Wq = (const float*)d_in[7];
    const float* bq = (const float*)d_in[8];
    const float* W3 = (const float*)d_in[9];
    const float* b3 = (const float*)d_in[10];
    const int* eidx = (const int*)d_in[11];
    const int* batch = (const int*)d_in[12];
    const int* sidx = (const int*)d_in[13];
    const int* seql = (const int*)d_in[14];

    int N = in_sizes[0] / Dq;
    int B = in_sizes[14];
    int E = in_sizes[11] / 2;
    float* out = (float*)d_out;

    k_mark<<<(N + 255) / 256, 256>>>(batch, N);
    k_scan<<<1, 1024>>>(seql, B, N);
    dim3 gm(Dq / 8, 4);
    k_mats<<<gm, 256>>>(Wg, W1, W2, W3);
    k_vecs<<<Hq, 128>>>(bg, b1, b2, b3, W1, W2, W3);
    k_packB<<<64, 128>>>();

    cudaFuncSetAttribute(k_gemm, cudaFuncAttributeMaxDynamicSharedMemorySize, GSM_TOTAL);
    k_gemm<<<N / 128, 256, GSM_TOTAL>>>(hidden);

    k_sessA<<<B, NTH>>>(hidden, eidx, sidx, seql, E, B);

    int zsm1 = (ZFB * 512 + 128 * 132) * (int)sizeof(float);
    cudaFuncSetAttribute(k_zu, cudaFuncAttributeMaxDynamicSharedMemorySize, zsm1);
    k_zu<<<(B + ZFB - 1) / ZFB, 256, zsm1>>>(B);

    k_sessB<<<B, NTH>>>(hidden, Wq, bq, B);

    int zsm2 = (ZFB * 512 + 128 * 68) * (int)sizeof(float);
    cudaFuncSetAttribute(k_zu2, cudaFuncAttributeMaxDynamicSharedMemorySize, zsm2);
    k_zu2<<<(B + ZFB - 1) / ZFB, 256, zsm2>>>(out, B);
}